// round 9
// baseline (speedup 1.0000x reference)
#include <cuda_runtime.h>
#include <cuda_fp16.h>
#include <cstdint>

#define NN 200000
#define NF 400000
#define NE (3*NF)

#define NBLK 196          // scan blocks (196*1024 >= NN)
#define KH 256            // h1 width
#define BM 64
#define BN 256
#define BK 16
#define NCHUNK (KH / BK)  // 16
#define ASTR 264          // As row stride (halves): 528B, conflict-free ldmatrix
#define BSTR 264
#define SM_AS_BYTES (BM * ASTR * 2)            // 33792
#define SM_BS_BYTES (2 * BK * BSTR * 2)        // 16896
#define SM_TOTAL (SM_AS_BYTES + SM_BS_BYTES)   // 50688

// -------- scratch (zero-initialized at module load; every replay restores) ----
__device__ int g_deg[NN];            // reset by k_gemm
__device__ float g_s1[3 * NN];       // reset by k_gemm
__device__ int g_flag[NBLK];         // reset by k_fill
__device__ float g_gsum[128];        // reset by k_final
__device__ int g_rowptr[NN + 1];
__device__ int g_cursor[NN];
__device__ int g_aggval[NBLK];
__device__ int g_incval[NBLK];
__device__ int g_colidx[NE];
__device__ __half g_t[(size_t)NN * 128];    // 51.2 MB (gathered)
__device__ __half g_u[(size_t)NN * 128];    // 51.2 MB (streamed)
__device__ __half g_Wc[256 * 256];          // [k][n]: fp16(W2l|W2r)

// ---- L1: face-parallel hist + pos aggregation + fp16 weight conversion -------
__global__ void k_hist(const int* __restrict__ face, const float* __restrict__ pos,
                       const float* __restrict__ W2l, const float* __restrict__ W2r) {
    int i = blockIdx.x * blockDim.x + threadIdx.x;
    if (i < 256 * 256) {
        int k = i >> 8, c = i & 255;
        float w = (c < 128) ? W2l[k * 128 + c] : W2r[k * 128 + (c - 128)];
        g_Wc[k * 256 + c] = __float2half_rn(w);
    }
    if (i >= NF) return;
    int v0 = face[i], v1 = face[NF + i], v2 = face[2 * NF + i];
    float p0x = pos[3 * v0 + 0], p0y = pos[3 * v0 + 1], p0z = pos[3 * v0 + 2];
    if (v0 != v1) {
        atomicAdd(&g_deg[v1], 1);
        atomicAdd(&g_s1[3 * v1 + 0], p0x);
        atomicAdd(&g_s1[3 * v1 + 1], p0y);
        atomicAdd(&g_s1[3 * v1 + 2], p0z);
    }
    if (v1 != v2) {
        atomicAdd(&g_deg[v2], 1);
        atomicAdd(&g_s1[3 * v2 + 0], pos[3 * v1 + 0]);
        atomicAdd(&g_s1[3 * v2 + 1], pos[3 * v1 + 1]);
        atomicAdd(&g_s1[3 * v2 + 2], pos[3 * v1 + 2]);
    }
    if (v0 != v2) {
        atomicAdd(&g_deg[v2], 1);
        atomicAdd(&g_s1[3 * v2 + 0], p0x);
        atomicAdd(&g_s1[3 * v2 + 1], p0y);
        atomicAdd(&g_s1[3 * v2 + 2], p0z);
    }
}

// ---- L2: single-pass decoupled-lookback scan (rowptr + cursor) ---------------
__global__ void k_scan() {
    __shared__ int s[1024];
    __shared__ int sprefix;
    int b = blockIdx.x;
    int tid = threadIdx.x;
    int i = b * 1024 + tid;
    int v = (i < NN) ? g_deg[i] : 0;
    s[tid] = v;
    __syncthreads();
    #pragma unroll
    for (int off = 1; off < 1024; off <<= 1) {
        int t = (tid >= off) ? s[tid - off] : 0;
        __syncthreads();
        s[tid] += t;
        __syncthreads();
    }
    int total = s[1023];
    if (tid == 0) {
        if (b == 0) {
            g_incval[0] = total;
            __threadfence();
            atomicExch(&g_flag[0], 2);
            sprefix = 0;
        } else {
            g_aggval[b] = total;
            __threadfence();
            atomicExch(&g_flag[b], 1);
            int prefix = 0;
            int j = b - 1;
            while (j >= 0) {
                int f;
                do { f = atomicAdd(&g_flag[j], 0); } while (f == 0);
                if (f == 2) { prefix += g_incval[j]; break; }
                prefix += g_aggval[j];
                j--;
            }
            g_incval[b] = prefix + total;
            __threadfence();
            atomicExch(&g_flag[b], 2);
            sprefix = prefix;
        }
    }
    __syncthreads();
    int p = sprefix;
    if (i < NN) {
        int r = p + s[tid] - v;   // exclusive
        g_rowptr[i] = r;
        g_cursor[i] = r;
    }
    if (b == NBLK - 1 && tid == 1023) g_rowptr[NN] = p + total;
}

// ---- L3: fill CSR (+ restore scan flags) --------------------------------------
__global__ void k_fill(const int* __restrict__ face) {
    int i = blockIdx.x * blockDim.x + threadIdx.x;
    if (i < NBLK) g_flag[i] = 0;            // restore invariant
    if (i >= NF) return;
    int v0 = face[i], v1 = face[NF + i], v2 = face[2 * NF + i];
    if (v0 != v1) g_colidx[atomicAdd(&g_cursor[v1], 1)] = v0;
    if (v1 != v2) g_colidx[atomicAdd(&g_cursor[v2], 1)] = v1;
    if (v0 != v2) g_colidx[atomicAdd(&g_cursor[v2], 1)] = v0;
}

// ---- L4 (PROFILED): FUSED layer1-dense + fp16 mma GEMM ------------------------
// Per CTA: 64 nodes. Phase 1: compute h1 tile (64x256 fp16) in SMEM from agg/pos.
// Phase 2: [t|u] = h1_tile @ Wc with register-staged double-buffered B.
// NN = 64 * 3125 exactly: no tail anywhere.
__global__ void __launch_bounds__(256, 2) k_gemm(
        const float* __restrict__ pos, const float* __restrict__ W1l,
        const float* __restrict__ W1r, const float* __restrict__ b1) {
    extern __shared__ char sm[];
    __half* As = (__half*)sm;                      // [64][ASTR]
    __half* Bs = (__half*)(sm + SM_AS_BYTES);      // [2][BK][BSTR]

    int tid = threadIdx.x;
    int warp = tid >> 5, lane = tid & 31;
    int wm = warp & 1, wn = warp >> 1;             // 2(M) x 4(N) warps
    int bm = blockIdx.x * BM;

    // ---------------- phase 1: h1 tile + B chunk 0 prefetch ----------------
    int nl = tid >> 2;                 // local node 0..63
    int part = tid & 3;                // column quarter
    int node = bm + nl;

    int deg = g_deg[node];
    float inv = 1.0f / fmaxf((float)deg, 1.0f);
    float ax = g_s1[3 * node + 0] * inv;
    float ay = g_s1[3 * node + 1] * inv;
    float az = g_s1[3 * node + 2] * inv;
    float px = pos[3 * node + 0], py = pos[3 * node + 1], pz = pos[3 * node + 2];

    // prefetch B chunk 0 (16x256 halves = 512 uint4; 2 per thread)
    uint4 breg[2];
    #pragma unroll
    for (int j = 0; j < 2; j++) {
        int idx = tid + 256 * j;
        int row = idx >> 5, cq = idx & 31;
        breg[j] = *(const uint4*)(g_Wc + (size_t)row * 256 + cq * 8);
    }

    // dense layer-1 for 64 columns of this node
    #pragma unroll 4
    for (int cc = 0; cc < 64; cc += 4) {
        int c = part * 64 + cc;
        float4 l0 = __ldg((const float4*)(W1l + c));
        float4 l1 = __ldg((const float4*)(W1l + 256 + c));
        float4 l2 = __ldg((const float4*)(W1l + 512 + c));
        float4 r0 = __ldg((const float4*)(W1r + c));
        float4 r1 = __ldg((const float4*)(W1r + 256 + c));
        float4 r2 = __ldg((const float4*)(W1r + 512 + c));
        float4 bb = __ldg((const float4*)(b1 + c));
        float h0 = fmaxf(bb.x + ax*l0.x + ay*l1.x + az*l2.x + px*r0.x + py*r1.x + pz*r2.x, 0.f);
        float h1 = fmaxf(bb.y + ax*l0.y + ay*l1.y + az*l2.y + px*r0.y + py*r1.y + pz*r2.y, 0.f);
        float h2 = fmaxf(bb.z + ax*l0.z + ay*l1.z + az*l2.z + px*r0.z + py*r1.z + pz*r2.z, 0.f);
        float h3 = fmaxf(bb.w + ax*l0.w + ay*l1.w + az*l2.w + px*r0.w + py*r1.w + pz*r2.w, 0.f);
        __half2 pA = __floats2half2_rn(h0, h1);
        __half2 pB = __floats2half2_rn(h2, h3);
        uint2 pk = make_uint2(*(unsigned*)&pA, *(unsigned*)&pB);
        *(uint2*)(As + nl * ASTR + c) = pk;
    }

    // store B chunk 0
    #pragma unroll
    for (int j = 0; j < 2; j++) {
        int idx = tid + 256 * j;
        int row = idx >> 5, cq = idx & 31;
        *(uint4*)(Bs + row * BSTR + cq * 8) = breg[j];
    }
    __syncthreads();

    // restore invariants (all reads of deg/s1 completed before the barrier)
    if (part == 0) {
        g_deg[node] = 0;
        g_s1[3 * node + 0] = 0.0f;
        g_s1[3 * node + 1] = 0.0f;
        g_s1[3 * node + 2] = 0.0f;
    }

    // ---------------- phase 2: mma pipeline ----------------
    float acc[2][8][4];
    #pragma unroll
    for (int mi = 0; mi < 2; mi++)
        #pragma unroll
        for (int ni = 0; ni < 8; ni++)
            #pragma unroll
            for (int q = 0; q < 4; q++) acc[mi][ni][q] = 0.0f;

    #pragma unroll 1
    for (int it = 0; it < NCHUNK; it++) {
        int cur = it & 1;
        // stage next B chunk into registers (overlaps with mma below)
        if (it < NCHUNK - 1) {
            int k0n = (it + 1) * BK;
            #pragma unroll
            for (int j = 0; j < 2; j++) {
                int idx = tid + 256 * j;
                int row = idx >> 5, cq = idx & 31;
                breg[j] = *(const uint4*)(g_Wc + (size_t)(k0n + row) * 256 + cq * 8);
            }
        }

        int k0 = it * BK;
        uint32_t a[2][4];
        #pragma unroll
        for (int mi = 0; mi < 2; mi++) {
            int r = wm * 32 + mi * 16 + (lane & 7) + 8 * ((lane >> 3) & 1);
            int cc = k0 + 8 * (lane >> 4);
            uint32_t addr = (uint32_t)__cvta_generic_to_shared(As + r * ASTR + cc);
            asm volatile("ldmatrix.sync.aligned.m8n8.x4.shared.b16 {%0,%1,%2,%3}, [%4];"
                         : "=r"(a[mi][0]), "=r"(a[mi][1]), "=r"(a[mi][2]), "=r"(a[mi][3])
                         : "r"(addr));
        }
        int rr = (lane & 7) + 8 * ((lane >> 3) & 1);
        #pragma unroll
        for (int np = 0; np < 4; np++) {
            int ncol = wn * 64 + np * 16 + 8 * (lane >> 4);
            uint32_t b[4];
            uint32_t baddr = (uint32_t)__cvta_generic_to_shared(Bs + cur * BK * BSTR + rr * BSTR + ncol);
            asm volatile("ldmatrix.sync.aligned.m8n8.x4.trans.shared.b16 {%0,%1,%2,%3}, [%4];"
                         : "=r"(b[0]), "=r"(b[1]), "=r"(b[2]), "=r"(b[3])
                         : "r"(baddr));
            #pragma unroll
            for (int mi = 0; mi < 2; mi++) {
                #pragma unroll
                for (int h = 0; h < 2; h++) {
                    int ni = np * 2 + h;
                    asm volatile(
                        "mma.sync.aligned.m16n8k16.row.col.f32.f16.f16.f32 "
                        "{%0,%1,%2,%3},{%4,%5,%6,%7},{%8,%9},{%0,%1,%2,%3};"
                        : "+f"(acc[mi][ni][0]), "+f"(acc[mi][ni][1]),
                          "+f"(acc[mi][ni][2]), "+f"(acc[mi][ni][3])
                        : "r"(a[mi][0]), "r"(a[mi][1]), "r"(a[mi][2]), "r"(a[mi][3]),
                          "r"(b[2 * h]), "r"(b[2 * h + 1]));
                }
            }
        }

        // commit staged B into the other buffer
        if (it < NCHUNK - 1) {
            #pragma unroll
            for (int j = 0; j < 2; j++) {
                int idx = tid + 256 * j;
                int row = idx >> 5, cq = idx & 31;
                *(uint4*)(Bs + (cur ^ 1) * BK * BSTR + row * BSTR + cq * 8) = breg[j];
            }
        }
        __syncthreads();
    }

    // epilogue: fp16 store, cols <128 -> g_t, cols >=128 -> g_u (no tail)
    int gid = lane >> 2, qid = lane & 3;
    #pragma unroll
    for (int mi = 0; mi < 2; mi++) {
        int r0 = bm + wm * 32 + mi * 16 + gid;
        int r1 = r0 + 8;
        #pragma unroll
        for (int ni = 0; ni < 8; ni++) {
            int col = wn * 64 + ni * 8 + qid * 2;
            __half* base0;
            int cc;
            if (col < 128) { base0 = g_t; cc = col; }
            else           { base0 = g_u; cc = col - 128; }
            __half2 p0 = __floats2half2_rn(acc[mi][ni][0], acc[mi][ni][1]);
            *(unsigned*)(base0 + (size_t)r0 * 128 + cc) = *(unsigned*)&p0;
            __half2 p1 = __floats2half2_rn(acc[mi][ni][2], acc[mi][ni][3]);
            *(unsigned*)(base0 + (size_t)r1 * 128 + cc) = *(unsigned*)&p1;
        }
    }
}

// ---- L5: layer-2 aggregate + relu + mean-pool ---------------------------------
__global__ void k_layer2(const float* __restrict__ b2) {
    __shared__ float gsh[128];
    if (threadIdx.x < 128) gsh[threadIdx.x] = 0.0f;
    __syncthreads();

    int wid = threadIdx.x >> 5, lane = threadIdx.x & 31;
    int gwarp = blockIdx.x * (blockDim.x >> 5) + wid;
    int nwarps = gridDim.x * (blockDim.x >> 5);
    float4 bl = ((const float4*)b2)[lane];

    float a0 = 0.f, a1 = 0.f, a2 = 0.f, a3 = 0.f;
    for (int node = gwarp; node < NN; node += nwarps) {
        int beg = g_rowptr[node], end = g_rowptr[node + 1];
        float s0 = 0.f, s1 = 0.f, s2 = 0.f, s3 = 0.f;
        #pragma unroll 4
        for (int j = beg; j < end; j++) {
            int src = g_colidx[j];
            uint2 tv = ((const uint2*)(g_t + (size_t)src * 128))[lane];
            float2 t01 = __half22float2(*(__half2*)&tv.x);
            float2 t23 = __half22float2(*(__half2*)&tv.y);
            s0 += t01.x; s1 += t01.y;
            s2 += t23.x; s3 += t23.y;
        }
        float inv = 1.0f / fmaxf((float)(end - beg), 1.0f);
        uint2 uv = ((const uint2*)(g_u + (size_t)node * 128))[lane];
        float2 u01 = __half22float2(*(__half2*)&uv.x);
        float2 u23 = __half22float2(*(__half2*)&uv.y);
        a0 += fmaxf(s0 * inv + u01.x + bl.x, 0.0f);
        a1 += fmaxf(s1 * inv + u01.y + bl.y, 0.0f);
        a2 += fmaxf(s2 * inv + u23.x + bl.z, 0.0f);
        a3 += fmaxf(s3 * inv + u23.y + bl.w, 0.0f);
    }
    atomicAdd(&gsh[lane * 4 + 0], a0);
    atomicAdd(&gsh[lane * 4 + 1], a1);
    atomicAdd(&gsh[lane * 4 + 2], a2);
    atomicAdd(&gsh[lane * 4 + 3], a3);
    __syncthreads();
    if (threadIdx.x < 128) atomicAdd(&g_gsum[threadIdx.x], gsh[threadIdx.x]);
}

// ---- L6: decoder + softmax + argmax (+ restore gsum) ---------------------------
__global__ void k_final(const float* __restrict__ Wd, const float* __restrict__ bd,
                        float* __restrict__ out, int out_size) {
    if (threadIdx.x != 0 || blockIdx.x != 0) return;
    float g[128];
    for (int c = 0; c < 128; c++) {
        g[c] = g_gsum[c] * (1.0f / (float)NN);
        g_gsum[c] = 0.0f;   // restore invariant
    }
    float lg[10];
    for (int j = 0; j < 10; j++) lg[j] = bd[j];
    for (int c = 0; c < 128; c++) {
        float gv = g[c];
        for (int j = 0; j < 10; j++) lg[j] += gv * Wd[c * 10 + j];
    }
    float m = lg[0];
    for (int j = 1; j < 10; j++) m = fmaxf(m, lg[j]);
    float e[10], s = 0.0f;
    for (int j = 0; j < 10; j++) { e[j] = expf(lg[j] - m); s += e[j]; }
    float invs = 1.0f / s;
    int am = 0;
    float best = -1.0f;
    for (int j = 0; j < 10; j++) {
        float p = e[j] * invs;
        if (j < out_size) out[j] = p;
        if (p > best) { best = p; am = j; }
    }
    for (int i = 10; i < out_size; i++) out[i] = (float)am;
}

// ---------------- launch --------------------------------------------------------
extern "C" void kernel_launch(void* const* d_in, const int* in_sizes, int n_in,
                              void* d_out, int out_size) {
    const float* pos = (const float*)d_in[0];
    const int*   face = (const int*)d_in[1];
    const float* W1l = (const float*)d_in[2];
    const float* W1r = (const float*)d_in[3];
    const float* b1  = (const float*)d_in[4];
    const float* W2l = (const float*)d_in[5];
    const float* W2r = (const float*)d_in[6];
    const float* b2  = (const float*)d_in[7];
    const float* Wd  = (const float*)d_in[8];
    const float* bd  = (const float*)d_in[9];
    float* out = (float*)d_out;

    cudaFuncSetAttribute(k_gemm, cudaFuncAttributeMaxDynamicSharedMemorySize, SM_TOTAL);

    k_hist   <<<(NF + 255) / 256, 256>>>(face, pos, W2l, W2r);      // 1
    k_scan   <<<NBLK, 1024>>>();                                    // 2
    k_fill   <<<(NF + 255) / 256, 256>>>(face);                     // 3
    k_gemm   <<<NN / BM, 256, SM_TOTAL>>>(pos, W1l, W1r, b1);       // 4  <- profiled
    k_layer2 <<<1184, 256>>>(b2);                                   // 5
    k_final  <<<1, 32>>>(Wd, bd, out, out_size);                    // 6
}

// round 10
// speedup vs baseline: 1.2849x; 1.2849x over previous
#include <cuda_runtime.h>
#include <cuda_fp16.h>
#include <cstdint>

#define NN 200000
#define NF 400000
#define NE (3*NF)

#define NBLK 196          // scan blocks (196*1024 >= NN)
#define KH 256            // h1 width
#define BM 64
#define BN 256
#define BK 32

// -------- scratch (zero-initialized at module load; every replay restores) ----
__device__ int g_deg[NN];            // reset by k_layer1g
__device__ float g_s1[3 * NN];       // reset by k_layer1g
__device__ int g_flag[NBLK];         // reset by k_fill
__device__ float g_gsum[128];        // reset by k_final
__device__ int g_rowptr[NN + 1];
__device__ int g_cursor[NN];
__device__ int g_aggval[NBLK];
__device__ int g_incval[NBLK];
__device__ int g_colidx[NE];
__device__ __half g_h1[(size_t)NN * 256];   // 102.4 MB
__device__ __half g_t[(size_t)NN * 128];    // 51.2 MB (gathered)
__device__ __half g_u[(size_t)NN * 128];    // 51.2 MB (streamed)
__device__ __half g_Wc[256 * 256];          // [k][n]: fp16(W2l|W2r)

// ---- L1: face-parallel hist + pos aggregation + fp16 weight conversion -------
__global__ void k_hist(const int* __restrict__ face, const float* __restrict__ pos,
                       const float* __restrict__ W2l, const float* __restrict__ W2r) {
    int i = blockIdx.x * blockDim.x + threadIdx.x;
    if (i < 256 * 256) {
        int k = i >> 8, c = i & 255;
        float w = (c < 128) ? W2l[k * 128 + c] : W2r[k * 128 + (c - 128)];
        g_Wc[k * 256 + c] = __float2half_rn(w);
    }
    if (i >= NF) return;
    int v0 = face[i], v1 = face[NF + i], v2 = face[2 * NF + i];
    float p0x = pos[3 * v0 + 0], p0y = pos[3 * v0 + 1], p0z = pos[3 * v0 + 2];
    if (v0 != v1) {
        atomicAdd(&g_deg[v1], 1);
        atomicAdd(&g_s1[3 * v1 + 0], p0x);
        atomicAdd(&g_s1[3 * v1 + 1], p0y);
        atomicAdd(&g_s1[3 * v1 + 2], p0z);
    }
    if (v1 != v2) {
        atomicAdd(&g_deg[v2], 1);
        atomicAdd(&g_s1[3 * v2 + 0], pos[3 * v1 + 0]);
        atomicAdd(&g_s1[3 * v2 + 1], pos[3 * v1 + 1]);
        atomicAdd(&g_s1[3 * v2 + 2], pos[3 * v1 + 2]);
    }
    if (v0 != v2) {
        atomicAdd(&g_deg[v2], 1);
        atomicAdd(&g_s1[3 * v2 + 0], p0x);
        atomicAdd(&g_s1[3 * v2 + 1], p0y);
        atomicAdd(&g_s1[3 * v2 + 2], p0z);
    }
}

// ---- L2: single-pass decoupled-lookback scan (rowptr + cursor) ---------------
__global__ void k_scan() {
    __shared__ int s[1024];
    __shared__ int sprefix;
    int b = blockIdx.x;
    int tid = threadIdx.x;
    int i = b * 1024 + tid;
    int v = (i < NN) ? g_deg[i] : 0;
    s[tid] = v;
    __syncthreads();
    #pragma unroll
    for (int off = 1; off < 1024; off <<= 1) {
        int t = (tid >= off) ? s[tid - off] : 0;
        __syncthreads();
        s[tid] += t;
        __syncthreads();
    }
    int total = s[1023];
    if (tid == 0) {
        if (b == 0) {
            g_incval[0] = total;
            __threadfence();
            atomicExch(&g_flag[0], 2);
            sprefix = 0;
        } else {
            g_aggval[b] = total;
            __threadfence();
            atomicExch(&g_flag[b], 1);
            int prefix = 0;
            int j = b - 1;
            while (j >= 0) {
                int f;
                do { f = atomicAdd(&g_flag[j], 0); } while (f == 0);
                if (f == 2) { prefix += g_incval[j]; break; }
                prefix += g_aggval[j];
                j--;
            }
            g_incval[b] = prefix + total;
            __threadfence();
            atomicExch(&g_flag[b], 2);
            sprefix = prefix;
        }
    }
    __syncthreads();
    int p = sprefix;
    if (i < NN) {
        int r = p + s[tid] - v;   // exclusive
        g_rowptr[i] = r;
        g_cursor[i] = r;
    }
    if (b == NBLK - 1 && tid == 1023) g_rowptr[NN] = p + total;
}

// ---- L3: fill CSR (+ restore scan flags) --------------------------------------
__global__ void k_fill(const int* __restrict__ face) {
    int i = blockIdx.x * blockDim.x + threadIdx.x;
    if (i < NBLK) g_flag[i] = 0;            // restore invariant
    if (i >= NF) return;
    int v0 = face[i], v1 = face[NF + i], v2 = face[2 * NF + i];
    if (v0 != v1) g_colidx[atomicAdd(&g_cursor[v1], 1)] = v0;
    if (v1 != v2) g_colidx[atomicAdd(&g_cursor[v2], 1)] = v1;
    if (v0 != v2) g_colidx[atomicAdd(&g_cursor[v2], 1)] = v0;
}

// ---- L4 (PROFILED): layer-1 as K=16 fp16 mma GEMM -----------------------------
// h1[64x256 per CTA] = relu([agg3|pos3|1|0pad] @ W1c), W1c = [W1l;W1r;b1;0pad].
// One mma K-step; cost ~= the 102MB g_h1 store. NN = 64*3125: no tail.
__global__ void __launch_bounds__(256) k_layer1g(
        const float* __restrict__ pos, const float* __restrict__ W1l,
        const float* __restrict__ W1r, const float* __restrict__ b1) {
    __shared__ __half As[64][24];    // 16 used cols; stride 48B (conflict-free)
    __shared__ __half Bs[16][264];

    int tid = threadIdx.x;
    int warp = tid >> 5, lane = tid & 31;
    int wm = warp & 1, wn = warp >> 1;   // 2(M) x 4(N) warps; warp tile 32x64
    int bm = blockIdx.x * BM;

    // build B tile: 16 x 256 fp16 from W1l/W1r/b1 (rows 7..15 zero)
    #pragma unroll
    for (int j = 0; j < 2; j++) {
        int idx = tid + 256 * j;
        int row = idx >> 5, cq = idx & 31;
        int c = cq * 8;
        float v[8];
        #pragma unroll
        for (int q = 0; q < 8; q++) {
            float w = 0.0f;
            if (row < 3)      w = W1l[row * 256 + c + q];
            else if (row < 6) w = W1r[(row - 3) * 256 + c + q];
            else if (row == 6) w = b1[c + q];
            v[q] = w;
        }
        __half2 h0 = __floats2half2_rn(v[0], v[1]);
        __half2 h1 = __floats2half2_rn(v[2], v[3]);
        __half2 h2 = __floats2half2_rn(v[4], v[5]);
        __half2 h3 = __floats2half2_rn(v[6], v[7]);
        *(uint4*)(&Bs[row][c]) = make_uint4(*(unsigned*)&h0, *(unsigned*)&h1,
                                            *(unsigned*)&h2, *(unsigned*)&h3);
    }
    // build A tile: one row per node = [ax,ay,az,px,py,pz,1,0,...0]
    if (tid < 64) {
        int node = bm + tid;
        int deg = g_deg[node];
        float inv = 1.0f / fmaxf((float)deg, 1.0f);
        float ax = g_s1[3 * node + 0] * inv;
        float ay = g_s1[3 * node + 1] * inv;
        float az = g_s1[3 * node + 2] * inv;
        float px = pos[3 * node + 0], py = pos[3 * node + 1], pz = pos[3 * node + 2];
        // restore invariants for next replay
        g_deg[node] = 0;
        g_s1[3 * node + 0] = 0.0f;
        g_s1[3 * node + 1] = 0.0f;
        g_s1[3 * node + 2] = 0.0f;
        __half2 c01 = __floats2half2_rn(ax, ay);
        __half2 c23 = __floats2half2_rn(az, px);
        __half2 c45 = __floats2half2_rn(py, pz);
        __half2 c67 = __floats2half2_rn(1.0f, 0.0f);
        *(uint4*)(&As[tid][0]) = make_uint4(*(unsigned*)&c01, *(unsigned*)&c23,
                                            *(unsigned*)&c45, *(unsigned*)&c67);
        *(uint4*)(&As[tid][8]) = make_uint4(0, 0, 0, 0);
    }
    __syncthreads();

    // single K=16 mma pass
    float acc[2][8][4];
    #pragma unroll
    for (int mi = 0; mi < 2; mi++)
        #pragma unroll
        for (int ni = 0; ni < 8; ni++)
            #pragma unroll
            for (int q = 0; q < 4; q++) acc[mi][ni][q] = 0.0f;

    uint32_t a[2][4];
    #pragma unroll
    for (int mi = 0; mi < 2; mi++) {
        int r = wm * 32 + mi * 16 + (lane & 7) + 8 * ((lane >> 3) & 1);
        int cc = 8 * (lane >> 4);
        uint32_t addr = (uint32_t)__cvta_generic_to_shared(&As[r][cc]);
        asm volatile("ldmatrix.sync.aligned.m8n8.x4.shared.b16 {%0,%1,%2,%3}, [%4];"
                     : "=r"(a[mi][0]), "=r"(a[mi][1]), "=r"(a[mi][2]), "=r"(a[mi][3])
                     : "r"(addr));
    }
    int rr = (lane & 7) + 8 * ((lane >> 3) & 1);
    #pragma unroll
    for (int np = 0; np < 4; np++) {
        int ncol = wn * 64 + np * 16 + 8 * (lane >> 4);
        uint32_t b[4];
        uint32_t baddr = (uint32_t)__cvta_generic_to_shared(&Bs[rr][ncol]);
        asm volatile("ldmatrix.sync.aligned.m8n8.x4.trans.shared.b16 {%0,%1,%2,%3}, [%4];"
                     : "=r"(b[0]), "=r"(b[1]), "=r"(b[2]), "=r"(b[3])
                     : "r"(baddr));
        #pragma unroll
        for (int mi = 0; mi < 2; mi++) {
            #pragma unroll
            for (int h = 0; h < 2; h++) {
                int ni = np * 2 + h;
                asm volatile(
                    "mma.sync.aligned.m16n8k16.row.col.f32.f16.f16.f32 "
                    "{%0,%1,%2,%3},{%4,%5,%6,%7},{%8,%9},{%0,%1,%2,%3};"
                    : "+f"(acc[mi][ni][0]), "+f"(acc[mi][ni][1]),
                      "+f"(acc[mi][ni][2]), "+f"(acc[mi][ni][3])
                    : "r"(a[mi][0]), "r"(a[mi][1]), "r"(a[mi][2]), "r"(a[mi][3]),
                      "r"(b[2 * h]), "r"(b[2 * h + 1]));
            }
        }
    }

    // epilogue: relu + fp16 store to g_h1
    int gid = lane >> 2, qid = lane & 3;
    #pragma unroll
    for (int mi = 0; mi < 2; mi++) {
        int r0 = bm + wm * 32 + mi * 16 + gid;
        int r1 = r0 + 8;
        #pragma unroll
        for (int ni = 0; ni < 8; ni++) {
            int col = wn * 64 + ni * 8 + qid * 2;
            __half2 p0 = __floats2half2_rn(fmaxf(acc[mi][ni][0], 0.0f),
                                           fmaxf(acc[mi][ni][1], 0.0f));
            *(unsigned*)(g_h1 + (size_t)r0 * 256 + col) = *(unsigned*)&p0;
            __half2 p1 = __floats2half2_rn(fmaxf(acc[mi][ni][2], 0.0f),
                                           fmaxf(acc[mi][ni][3], 0.0f));
            *(unsigned*)(g_h1 + (size_t)r1 * 256 + col) = *(unsigned*)&p1;
        }
    }
}

// ---- L5: fp16 mma GEMM  [t|u] = h1 @ Wc (proven R8 version) -------------------
__global__ void __launch_bounds__(256, 2) k_gemm() {
    __shared__ __half As[BM][BK + 24];   // stride 112B (conflict-free ldmatrix)
    __shared__ __half Bs[BK][BN + 8];    // stride 528B

    int tid = threadIdx.x;
    int warp = tid >> 5, lane = tid & 31;
    int wm = warp & 1, wn = warp >> 1;   // 2(M) x 4(N) warps
    int bm = blockIdx.x * BM;

    float c[2][8][4];
    #pragma unroll
    for (int mi = 0; mi < 2; mi++)
        #pragma unroll
        for (int ni = 0; ni < 8; ni++)
            #pragma unroll
            for (int q = 0; q < 4; q++) c[mi][ni][q] = 0.0f;

    for (int k0 = 0; k0 < KH; k0 += BK) {
        {
            int row = tid >> 2, cq = tid & 3;
            *(uint4*)(&As[row][cq * 8]) =
                *(const uint4*)(g_h1 + (size_t)(bm + row) * 256 + k0 + cq * 8);
        }
        #pragma unroll
        for (int r = 0; r < 4; r++) {
            int u = tid + 256 * r;
            int row = u >> 5, cq = u & 31;
            *(uint4*)(&Bs[row][cq * 8]) =
                *(const uint4*)(g_Wc + (size_t)(k0 + row) * 256 + cq * 8);
        }
        __syncthreads();

        #pragma unroll
        for (int kk = 0; kk < BK; kk += 16) {
            uint32_t a[2][4];
            #pragma unroll
            for (int mi = 0; mi < 2; mi++) {
                int r = wm * 32 + mi * 16 + (lane & 7) + 8 * ((lane >> 3) & 1);
                int cc = kk + 8 * (lane >> 4);
                uint32_t addr = (uint32_t)__cvta_generic_to_shared(&As[r][cc]);
                asm volatile("ldmatrix.sync.aligned.m8n8.x4.shared.b16 {%0,%1,%2,%3}, [%4];"
                             : "=r"(a[mi][0]), "=r"(a[mi][1]), "=r"(a[mi][2]), "=r"(a[mi][3])
                             : "r"(addr));
            }
            int rr = kk + (lane & 7) + 8 * ((lane >> 3) & 1);
            #pragma unroll
            for (int np = 0; np < 4; np++) {
                int ncol = wn * 64 + np * 16 + 8 * (lane >> 4);
                uint32_t b[4];
                uint32_t baddr = (uint32_t)__cvta_generic_to_shared(&Bs[rr][ncol]);
                asm volatile("ldmatrix.sync.aligned.m8n8.x4.trans.shared.b16 {%0,%1,%2,%3}, [%4];"
                             : "=r"(b[0]), "=r"(b[1]), "=r"(b[2]), "=r"(b[3])
                             : "r"(baddr));
                #pragma unroll
                for (int mi = 0; mi < 2; mi++) {
                    #pragma unroll
                    for (int h = 0; h < 2; h++) {
                        int ni = np * 2 + h;
                        asm volatile(
                            "mma.sync.aligned.m16n8k16.row.col.f32.f16.f16.f32 "
                            "{%0,%1,%2,%3},{%4,%5,%6,%7},{%8,%9},{%0,%1,%2,%3};"
                            : "+f"(c[mi][ni][0]), "+f"(c[mi][ni][1]),
                              "+f"(c[mi][ni][2]), "+f"(c[mi][ni][3])
                            : "r"(a[mi][0]), "r"(a[mi][1]), "r"(a[mi][2]), "r"(a[mi][3]),
                              "r"(b[2 * h]), "r"(b[2 * h + 1]));
                    }
                }
            }
        }
        __syncthreads();
    }

    int gid = lane >> 2, qid = lane & 3;
    #pragma unroll
    for (int mi = 0; mi < 2; mi++) {
        int r0 = bm + wm * 32 + mi * 16 + gid;
        int r1 = r0 + 8;
        #pragma unroll
        for (int ni = 0; ni < 8; ni++) {
            int col = wn * 64 + ni * 8 + qid * 2;
            __half* base0;
            int cc;
            if (col < 128) { base0 = g_t; cc = col; }
            else           { base0 = g_u; cc = col - 128; }
            __half2 p0 = __floats2half2_rn(c[mi][ni][0], c[mi][ni][1]);
            *(unsigned*)(base0 + (size_t)r0 * 128 + cc) = *(unsigned*)&p0;
            __half2 p1 = __floats2half2_rn(c[mi][ni][2], c[mi][ni][3]);
            *(unsigned*)(base0 + (size_t)r1 * 128 + cc) = *(unsigned*)&p1;
        }
    }
}

// ---- L6: layer-2 aggregate + relu + mean-pool ---------------------------------
__global__ void k_layer2(const float* __restrict__ b2) {
    __shared__ float gsh[128];
    if (threadIdx.x < 128) gsh[threadIdx.x] = 0.0f;
    __syncthreads();

    int wid = threadIdx.x >> 5, lane = threadIdx.x & 31;
    int gwarp = blockIdx.x * (blockDim.x >> 5) + wid;
    int nwarps = gridDim.x * (blockDim.x >> 5);
    float4 bl = ((const float4*)b2)[lane];

    float a0 = 0.f, a1 = 0.f, a2 = 0.f, a3 = 0.f;
    for (int node = gwarp; node < NN; node += nwarps) {
        int beg = g_rowptr[node], end = g_rowptr[node + 1];
        float s0 = 0.f, s1 = 0.f, s2 = 0.f, s3 = 0.f;
        #pragma unroll 4
        for (int j = beg; j < end; j++) {
            int src = g_colidx[j];
            uint2 tv = ((const uint2*)(g_t + (size_t)src * 128))[lane];
            float2 t01 = __half22float2(*(__half2*)&tv.x);
            float2 t23 = __half22float2(*(__half2*)&tv.y);
            s0 += t01.x; s1 += t01.y;
            s2 += t23.x; s3 += t23.y;
        }
        float inv = 1.0f / fmaxf((float)(end - beg), 1.0f);
        uint2 uv = ((const uint2*)(g_u + (size_t)node * 128))[lane];
        float2 u01 = __half22float2(*(__half2*)&uv.x);
        float2 u23 = __half22float2(*(__half2*)&uv.y);
        a0 += fmaxf(s0 * inv + u01.x + bl.x, 0.0f);
        a1 += fmaxf(s1 * inv + u01.y + bl.y, 0.0f);
        a2 += fmaxf(s2 * inv + u23.x + bl.z, 0.0f);
        a3 += fmaxf(s3 * inv + u23.y + bl.w, 0.0f);
    }
    atomicAdd(&gsh[lane * 4 + 0], a0);
    atomicAdd(&gsh[lane * 4 + 1], a1);
    atomicAdd(&gsh[lane * 4 + 2], a2);
    atomicAdd(&gsh[lane * 4 + 3], a3);
    __syncthreads();
    if (threadIdx.x < 128) atomicAdd(&g_gsum[threadIdx.x], gsh[threadIdx.x]);
}

// ---- L7: decoder + softmax + argmax (+ restore gsum) ---------------------------
__global__ void k_final(const float* __restrict__ Wd, const float* __restrict__ bd,
                        float* __restrict__ out, int out_size) {
    if (threadIdx.x != 0 || blockIdx.x != 0) return;
    float g[128];
    for (int c = 0; c < 128; c++) {
        g[c] = g_gsum[c] * (1.0f / (float)NN);
        g_gsum[c] = 0.0f;   // restore invariant
    }
    float lg[10];
    for (int j = 0; j < 10; j++) lg[j] = bd[j];
    for (int c = 0; c < 128; c++) {
        float gv = g[c];
        for (int j = 0; j < 10; j++) lg[j] += gv * Wd[c * 10 + j];
    }
    float m = lg[0];
    for (int j = 1; j < 10; j++) m = fmaxf(m, lg[j]);
    float e[10], s = 0.0f;
    for (int j = 0; j < 10; j++) { e[j] = expf(lg[j] - m); s += e[j]; }
    float invs = 1.0f / s;
    int am = 0;
    float best = -1.0f;
    for (int j = 0; j < 10; j++) {
        float p = e[j] * invs;
        if (j < out_size) out[j] = p;
        if (p > best) { best = p; am = j; }
    }
    for (int i = 10; i < out_size; i++) out[i] = (float)am;
}

// ---------------- launch --------------------------------------------------------
extern "C" void kernel_launch(void* const* d_in, const int* in_sizes, int n_in,
                              void* d_out, int out_size) {
    const float* pos = (const float*)d_in[0];
    const int*   face = (const int*)d_in[1];
    const float* W1l = (const float*)d_in[2];
    const float* W1r = (const float*)d_in[3];
    const float* b1  = (const float*)d_in[4];
    const float* W2l = (const float*)d_in[5];
    const float* W2r = (const float*)d_in[6];
    const float* b2  = (const float*)d_in[7];
    const float* Wd  = (const float*)d_in[8];
    const float* bd  = (const float*)d_in[9];
    float* out = (float*)d_out;

    k_hist    <<<(NF + 255) / 256, 256>>>(face, pos, W2l, W2r);  // 1
    k_scan    <<<NBLK, 1024>>>();                                // 2
    k_fill    <<<(NF + 255) / 256, 256>>>(face);                 // 3
    k_layer1g <<<NN / BM, 256>>>(pos, W1l, W1r, b1);             // 4  <- profiled
    k_gemm    <<<NN / BM, 256>>>();                              // 5
    k_layer2  <<<1184, 256>>>(b2);                               // 6
    k_final   <<<1, 32>>>(Wd, bd, out, out_size);                // 7
}

// round 11
// speedup vs baseline: 1.5035x; 1.1702x over previous
#include <cuda_runtime.h>
#include <cuda_fp16.h>
#include <cstdint>

#define NN 200000
#define NF 400000
#define NE (3*NF)

#define NBLK 196          // scan blocks (196*1024 >= NN)
#define KH 256            // h1 width
#define BM 64
#define BN 256
#define BK 32
#define ASTR 264          // SMEM row strides (multiple of 8 halves, conflict-free)
#define SM_TOTAL ((64 * ASTR + 32 * ASTR) * 2)   // 50688 bytes

// -------- scratch (zero-initialized at module load; every replay restores) ----
__device__ int g_deg[NN];            // reset by k_gemm phase 1
__device__ float g_s1[3 * NN];       // reset by k_gemm phase 1
__device__ int g_flag[NBLK];         // reset by k_fill
__device__ float g_gsum[128];        // reset by k_final
__device__ int g_rowptr[NN + 1];
__device__ int g_cursor[NN];
__device__ int g_aggval[NBLK];
__device__ int g_incval[NBLK];
__device__ int g_colidx[NE];
__device__ __half g_t[(size_t)NN * 128];    // 51.2 MB (gathered)
__device__ __half g_u[(size_t)NN * 128];    // 51.2 MB (streamed)
__device__ __half g_Wc[256 * 256];          // [k][n]: fp16(W2l|W2r)

// ---- L1: face-parallel hist + pos aggregation + fp16 weight conversion -------
__global__ void k_hist(const int* __restrict__ face, const float* __restrict__ pos,
                       const float* __restrict__ W2l, const float* __restrict__ W2r) {
    int i = blockIdx.x * blockDim.x + threadIdx.x;
    if (i < 256 * 256) {
        int k = i >> 8, c = i & 255;
        float w = (c < 128) ? W2l[k * 128 + c] : W2r[k * 128 + (c - 128)];
        g_Wc[k * 256 + c] = __float2half_rn(w);
    }
    if (i >= NF) return;
    int v0 = face[i], v1 = face[NF + i], v2 = face[2 * NF + i];
    float p0x = pos[3 * v0 + 0], p0y = pos[3 * v0 + 1], p0z = pos[3 * v0 + 2];
    if (v0 != v1) {
        atomicAdd(&g_deg[v1], 1);
        atomicAdd(&g_s1[3 * v1 + 0], p0x);
        atomicAdd(&g_s1[3 * v1 + 1], p0y);
        atomicAdd(&g_s1[3 * v1 + 2], p0z);
    }
    if (v1 != v2) {
        atomicAdd(&g_deg[v2], 1);
        atomicAdd(&g_s1[3 * v2 + 0], pos[3 * v1 + 0]);
        atomicAdd(&g_s1[3 * v2 + 1], pos[3 * v1 + 1]);
        atomicAdd(&g_s1[3 * v2 + 2], pos[3 * v1 + 2]);
    }
    if (v0 != v2) {
        atomicAdd(&g_deg[v2], 1);
        atomicAdd(&g_s1[3 * v2 + 0], p0x);
        atomicAdd(&g_s1[3 * v2 + 1], p0y);
        atomicAdd(&g_s1[3 * v2 + 2], p0z);
    }
}

// ---- L2: single-pass decoupled-lookback scan (rowptr + cursor) ---------------
__global__ void k_scan() {
    __shared__ int s[1024];
    __shared__ int sprefix;
    int b = blockIdx.x;
    int tid = threadIdx.x;
    int i = b * 1024 + tid;
    int v = (i < NN) ? g_deg[i] : 0;
    s[tid] = v;
    __syncthreads();
    #pragma unroll
    for (int off = 1; off < 1024; off <<= 1) {
        int t = (tid >= off) ? s[tid - off] : 0;
        __syncthreads();
        s[tid] += t;
        __syncthreads();
    }
    int total = s[1023];
    if (tid == 0) {
        if (b == 0) {
            g_incval[0] = total;
            __threadfence();
            atomicExch(&g_flag[0], 2);
            sprefix = 0;
        } else {
            g_aggval[b] = total;
            __threadfence();
            atomicExch(&g_flag[b], 1);
            int prefix = 0;
            int j = b - 1;
            while (j >= 0) {
                int f;
                do { f = atomicAdd(&g_flag[j], 0); } while (f == 0);
                if (f == 2) { prefix += g_incval[j]; break; }
                prefix += g_aggval[j];
                j--;
            }
            g_incval[b] = prefix + total;
            __threadfence();
            atomicExch(&g_flag[b], 2);
            sprefix = prefix;
        }
    }
    __syncthreads();
    int p = sprefix;
    if (i < NN) {
        int r = p + s[tid] - v;   // exclusive
        g_rowptr[i] = r;
        g_cursor[i] = r;
    }
    if (b == NBLK - 1 && tid == 1023) g_rowptr[NN] = p + total;
}

// ---- L3: fill CSR (+ restore scan flags) --------------------------------------
__global__ void k_fill(const int* __restrict__ face) {
    int i = blockIdx.x * blockDim.x + threadIdx.x;
    if (i < NBLK) g_flag[i] = 0;            // restore invariant
    if (i >= NF) return;
    int v0 = face[i], v1 = face[NF + i], v2 = face[2 * NF + i];
    if (v0 != v1) g_colidx[atomicAdd(&g_cursor[v1], 1)] = v0;
    if (v1 != v2) g_colidx[atomicAdd(&g_cursor[v2], 1)] = v1;
    if (v0 != v2) g_colidx[atomicAdd(&g_cursor[v2], 1)] = v0;
}

// ---- L4 (PROFILED): FUSED layer1-mma + layer2-dense GEMM ----------------------
// Phase 1: h1 tile (64x256) = relu([agg|pos|1|0] @ W1c) via one K=16 mma,
//          fragments stored fp16 into SMEM-resident As (never touches global).
// Phase 2: [t|u] = As @ Wc, K=256, B tiles streamed from g_Wc.
// NN = 64 * 3125 exactly: no tail.
__global__ void __launch_bounds__(256, 2) k_gemm(
        const float* __restrict__ pos, const float* __restrict__ W1l,
        const float* __restrict__ W1r, const float* __restrict__ b1) {
    extern __shared__ __half sm[];
    __half* As = sm;                 // [64][ASTR] : A16 input, then h1 tile
    __half* Bs = sm + 64 * ASTR;     // [32][ASTR] : W1 tile, then Wc chunks

    int tid = threadIdx.x;
    int warp = tid >> 5, lane = tid & 31;
    int wm = warp & 1, wn = warp >> 1;   // 2(M) x 4(N) warps; warp tile 32x64
    int bm = blockIdx.x * BM;

    // ------------- phase 1: build A16 + W1 tile -------------
    // W1 tile: 16 x 256 fp16 (rows: 0-2 W1l, 3-5 W1r, 6 b1, 7-15 zero)
    #pragma unroll
    for (int j = 0; j < 2; j++) {
        int idx = tid + 256 * j;
        int row = idx >> 5, cq = idx & 31;
        int c = cq * 8;
        float v[8];
        #pragma unroll
        for (int q = 0; q < 8; q++) {
            float w = 0.0f;
            if (row < 3)       w = W1l[row * 256 + c + q];
            else if (row < 6)  w = W1r[(row - 3) * 256 + c + q];
            else if (row == 6) w = b1[c + q];
            v[q] = w;
        }
        __half2 h0 = __floats2half2_rn(v[0], v[1]);
        __half2 h1 = __floats2half2_rn(v[2], v[3]);
        __half2 h2 = __floats2half2_rn(v[4], v[5]);
        __half2 h3 = __floats2half2_rn(v[6], v[7]);
        *(uint4*)(Bs + row * ASTR + c) = make_uint4(*(unsigned*)&h0, *(unsigned*)&h1,
                                                    *(unsigned*)&h2, *(unsigned*)&h3);
    }
    // A16: one row per node = [ax,ay,az,px,py,pz,1,0,...,0]
    if (tid < 64) {
        int node = bm + tid;
        int deg = g_deg[node];
        float inv = 1.0f / fmaxf((float)deg, 1.0f);
        float ax = g_s1[3 * node + 0] * inv;
        float ay = g_s1[3 * node + 1] * inv;
        float az = g_s1[3 * node + 2] * inv;
        float px = pos[3 * node + 0], py = pos[3 * node + 1], pz = pos[3 * node + 2];
        // restore invariants for next replay
        g_deg[node] = 0;
        g_s1[3 * node + 0] = 0.0f;
        g_s1[3 * node + 1] = 0.0f;
        g_s1[3 * node + 2] = 0.0f;
        __half2 c01 = __floats2half2_rn(ax, ay);
        __half2 c23 = __floats2half2_rn(az, px);
        __half2 c45 = __floats2half2_rn(py, pz);
        __half2 c67 = __floats2half2_rn(1.0f, 0.0f);
        *(uint4*)(As + tid * ASTR + 0) = make_uint4(*(unsigned*)&c01, *(unsigned*)&c23,
                                                    *(unsigned*)&c45, *(unsigned*)&c67);
        *(uint4*)(As + tid * ASTR + 8) = make_uint4(0, 0, 0, 0);
    }
    __syncthreads();

    // ------------- phase 1: K=16 mma -> h1 fragments -------------
    float acc[2][8][4];
    #pragma unroll
    for (int mi = 0; mi < 2; mi++)
        #pragma unroll
        for (int ni = 0; ni < 8; ni++)
            #pragma unroll
            for (int q = 0; q < 4; q++) acc[mi][ni][q] = 0.0f;

    {
        uint32_t a[2][4];
        #pragma unroll
        for (int mi = 0; mi < 2; mi++) {
            int r = wm * 32 + mi * 16 + (lane & 7) + 8 * ((lane >> 3) & 1);
            int cc = 8 * (lane >> 4);
            uint32_t addr = (uint32_t)__cvta_generic_to_shared(As + r * ASTR + cc);
            asm volatile("ldmatrix.sync.aligned.m8n8.x4.shared.b16 {%0,%1,%2,%3}, [%4];"
                         : "=r"(a[mi][0]), "=r"(a[mi][1]), "=r"(a[mi][2]), "=r"(a[mi][3])
                         : "r"(addr));
        }
        int rr = (lane & 7) + 8 * ((lane >> 3) & 1);
        #pragma unroll
        for (int np = 0; np < 4; np++) {
            int ncol = wn * 64 + np * 16 + 8 * (lane >> 4);
            uint32_t b[4];
            uint32_t baddr = (uint32_t)__cvta_generic_to_shared(Bs + rr * ASTR + ncol);
            asm volatile("ldmatrix.sync.aligned.m8n8.x4.trans.shared.b16 {%0,%1,%2,%3}, [%4];"
                         : "=r"(b[0]), "=r"(b[1]), "=r"(b[2]), "=r"(b[3])
                         : "r"(baddr));
            #pragma unroll
            for (int mi = 0; mi < 2; mi++) {
                #pragma unroll
                for (int h = 0; h < 2; h++) {
                    int ni = np * 2 + h;
                    asm volatile(
                        "mma.sync.aligned.m16n8k16.row.col.f32.f16.f16.f32 "
                        "{%0,%1,%2,%3},{%4,%5,%6,%7},{%8,%9},{%0,%1,%2,%3};"
                        : "+f"(acc[mi][ni][0]), "+f"(acc[mi][ni][1]),
                          "+f"(acc[mi][ni][2]), "+f"(acc[mi][ni][3])
                        : "r"(a[mi][0]), "r"(a[mi][1]), "r"(a[mi][2]), "r"(a[mi][3]),
                          "r"(b[2 * h]), "r"(b[2 * h + 1]));
                }
            }
        }
    }
    __syncthreads();   // all warps done reading A16/W1 tiles

    // relu + store h1 fragments into SMEM-resident As (full 64 x 256)
    {
        int gid = lane >> 2, qid = lane & 3;
        #pragma unroll
        for (int mi = 0; mi < 2; mi++) {
            int r0 = wm * 32 + mi * 16 + gid;
            int r1 = r0 + 8;
            #pragma unroll
            for (int ni = 0; ni < 8; ni++) {
                int col = wn * 64 + ni * 8 + qid * 2;
                __half2 p0 = __floats2half2_rn(fmaxf(acc[mi][ni][0], 0.0f),
                                               fmaxf(acc[mi][ni][1], 0.0f));
                *(unsigned*)(As + r0 * ASTR + col) = *(unsigned*)&p0;
                __half2 p1 = __floats2half2_rn(fmaxf(acc[mi][ni][2], 0.0f),
                                               fmaxf(acc[mi][ni][3], 0.0f));
                *(unsigned*)(As + r1 * ASTR + col) = *(unsigned*)&p1;
            }
        }
    }
    __syncthreads();

    // ------------- phase 2: [t|u] = As @ Wc -------------
    #pragma unroll
    for (int mi = 0; mi < 2; mi++)
        #pragma unroll
        for (int ni = 0; ni < 8; ni++)
            #pragma unroll
            for (int q = 0; q < 4; q++) acc[mi][ni][q] = 0.0f;

    #pragma unroll 1
    for (int k0 = 0; k0 < KH; k0 += BK) {
        // B tile: 32 x 256 fp16 (4 uint4 per thread)
        #pragma unroll
        for (int r = 0; r < 4; r++) {
            int u = tid + 256 * r;
            int row = u >> 5, cq = u & 31;
            *(uint4*)(Bs + row * ASTR + cq * 8) =
                *(const uint4*)(g_Wc + (size_t)(k0 + row) * 256 + cq * 8);
        }
        __syncthreads();

        #pragma unroll
        for (int kk = 0; kk < BK; kk += 16) {
            uint32_t a[2][4];
            #pragma unroll
            for (int mi = 0; mi < 2; mi++) {
                int r = wm * 32 + mi * 16 + (lane & 7) + 8 * ((lane >> 3) & 1);
                int cc = k0 + kk + 8 * (lane >> 4);
                uint32_t addr = (uint32_t)__cvta_generic_to_shared(As + r * ASTR + cc);
                asm volatile("ldmatrix.sync.aligned.m8n8.x4.shared.b16 {%0,%1,%2,%3}, [%4];"
                             : "=r"(a[mi][0]), "=r"(a[mi][1]), "=r"(a[mi][2]), "=r"(a[mi][3])
                             : "r"(addr));
            }
            int rr = kk + (lane & 7) + 8 * ((lane >> 3) & 1);
            #pragma unroll
            for (int np = 0; np < 4; np++) {
                int ncol = wn * 64 + np * 16 + 8 * (lane >> 4);
                uint32_t b[4];
                uint32_t baddr = (uint32_t)__cvta_generic_to_shared(Bs + rr * ASTR + ncol);
                asm volatile("ldmatrix.sync.aligned.m8n8.x4.trans.shared.b16 {%0,%1,%2,%3}, [%4];"
                             : "=r"(b[0]), "=r"(b[1]), "=r"(b[2]), "=r"(b[3])
                             : "r"(baddr));
                #pragma unroll
                for (int mi = 0; mi < 2; mi++) {
                    #pragma unroll
                    for (int h = 0; h < 2; h++) {
                        int ni = np * 2 + h;
                        asm volatile(
                            "mma.sync.aligned.m16n8k16.row.col.f32.f16.f16.f32 "
                            "{%0,%1,%2,%3},{%4,%5,%6,%7},{%8,%9},{%0,%1,%2,%3};"
                            : "+f"(acc[mi][ni][0]), "+f"(acc[mi][ni][1]),
                              "+f"(acc[mi][ni][2]), "+f"(acc[mi][ni][3])
                            : "r"(a[mi][0]), "r"(a[mi][1]), "r"(a[mi][2]), "r"(a[mi][3]),
                              "r"(b[2 * h]), "r"(b[2 * h + 1]));
                    }
                }
            }
        }
        __syncthreads();
    }

    // epilogue: fp16 store, cols <128 -> g_t, cols >=128 -> g_u (no tail)
    int gid = lane >> 2, qid = lane & 3;
    #pragma unroll
    for (int mi = 0; mi < 2; mi++) {
        int r0 = bm + wm * 32 + mi * 16 + gid;
        int r1 = r0 + 8;
        #pragma unroll
        for (int ni = 0; ni < 8; ni++) {
            int col = wn * 64 + ni * 8 + qid * 2;
            __half* base0;
            int cc;
            if (col < 128) { base0 = g_t; cc = col; }
            else           { base0 = g_u; cc = col - 128; }
            __half2 p0 = __floats2half2_rn(acc[mi][ni][0], acc[mi][ni][1]);
            *(unsigned*)(base0 + (size_t)r0 * 128 + cc) = *(unsigned*)&p0;
            __half2 p1 = __floats2half2_rn(acc[mi][ni][2], acc[mi][ni][3]);
            *(unsigned*)(base0 + (size_t)r1 * 128 + cc) = *(unsigned*)&p1;
        }
    }
}

// ---- L5: layer-2 aggregate + relu + mean-pool ---------------------------------
__global__ void k_layer2(const float* __restrict__ b2) {
    __shared__ float gsh[128];
    if (threadIdx.x < 128) gsh[threadIdx.x] = 0.0f;
    __syncthreads();

    int wid = threadIdx.x >> 5, lane = threadIdx.x & 31;
    int gwarp = blockIdx.x * (blockDim.x >> 5) + wid;
    int nwarps = gridDim.x * (blockDim.x >> 5);
    float4 bl = ((const float4*)b2)[lane];

    float a0 = 0.f, a1 = 0.f, a2 = 0.f, a3 = 0.f;
    for (int node = gwarp; node < NN; node += nwarps) {
        int beg = g_rowptr[node], end = g_rowptr[node + 1];
        float s0 = 0.f, s1 = 0.f, s2 = 0.f, s3 = 0.f;
        #pragma unroll 4
        for (int j = beg; j < end; j++) {
            int src = g_colidx[j];
            uint2 tv = ((const uint2*)(g_t + (size_t)src * 128))[lane];
            float2 t01 = __half22float2(*(__half2*)&tv.x);
            float2 t23 = __half22float2(*(__half2*)&tv.y);
            s0 += t01.x; s1 += t01.y;
            s2 += t23.x; s3 += t23.y;
        }
        float inv = 1.0f / fmaxf((float)(end - beg), 1.0f);
        uint2 uv = ((const uint2*)(g_u + (size_t)node * 128))[lane];
        float2 u01 = __half22float2(*(__half2*)&uv.x);
        float2 u23 = __half22float2(*(__half2*)&uv.y);
        a0 += fmaxf(s0 * inv + u01.x + bl.x, 0.0f);
        a1 += fmaxf(s1 * inv + u01.y + bl.y, 0.0f);
        a2 += fmaxf(s2 * inv + u23.x + bl.z, 0.0f);
        a3 += fmaxf(s3 * inv + u23.y + bl.w, 0.0f);
    }
    atomicAdd(&gsh[lane * 4 + 0], a0);
    atomicAdd(&gsh[lane * 4 + 1], a1);
    atomicAdd(&gsh[lane * 4 + 2], a2);
    atomicAdd(&gsh[lane * 4 + 3], a3);
    __syncthreads();
    if (threadIdx.x < 128) atomicAdd(&g_gsum[threadIdx.x], gsh[threadIdx.x]);
}

// ---- L6: decoder + softmax + argmax (+ restore gsum) ---------------------------
__global__ void k_final(const float* __restrict__ Wd, const float* __restrict__ bd,
                        float* __restrict__ out, int out_size) {
    if (threadIdx.x != 0 || blockIdx.x != 0) return;
    float g[128];
    for (int c = 0; c < 128; c++) {
        g[c] = g_gsum[c] * (1.0f / (float)NN);
        g_gsum[c] = 0.0f;   // restore invariant
    }
    float lg[10];
    for (int j = 0; j < 10; j++) lg[j] = bd[j];
    for (int c = 0; c < 128; c++) {
        float gv = g[c];
        for (int j = 0; j < 10; j++) lg[j] += gv * Wd[c * 10 + j];
    }
    float m = lg[0];
    for (int j = 1; j < 10; j++) m = fmaxf(m, lg[j]);
    float e[10], s = 0.0f;
    for (int j = 0; j < 10; j++) { e[j] = expf(lg[j] - m); s += e[j]; }
    float invs = 1.0f / s;
    int am = 0;
    float best = -1.0f;
    for (int j = 0; j < 10; j++) {
        float p = e[j] * invs;
        if (j < out_size) out[j] = p;
        if (p > best) { best = p; am = j; }
    }
    for (int i = 10; i < out_size; i++) out[i] = (float)am;
}

// ---------------- launch --------------------------------------------------------
extern "C" void kernel_launch(void* const* d_in, const int* in_sizes, int n_in,
                              void* d_out, int out_size) {
    const float* pos = (const float*)d_in[0];
    const int*   face = (const int*)d_in[1];
    const float* W1l = (const float*)d_in[2];
    const float* W1r = (const float*)d_in[3];
    const float* b1  = (const float*)d_in[4];
    const float* W2l = (const float*)d_in[5];
    const float* W2r = (const float*)d_in[6];
    const float* b2  = (const float*)d_in[7];
    const float* Wd  = (const float*)d_in[8];
    const float* bd  = (const float*)d_in[9];
    float* out = (float*)d_out;

    cudaFuncSetAttribute(k_gemm, cudaFuncAttributeMaxDynamicSharedMemorySize, SM_TOTAL);

    k_hist   <<<(NF + 255) / 256, 256>>>(face, pos, W2l, W2r);     // 1
    k_scan   <<<NBLK, 1024>>>();                                   // 2
    k_fill   <<<(NF + 255) / 256, 256>>>(face);                    // 3
    k_gemm   <<<NN / BM, 256, SM_TOTAL>>>(pos, W1l, W1r, b1);      // 4  <- profiled
    k_layer2 <<<1184, 256>>>(b2);                                  // 5
    k_final  <<<1, 32>>>(Wd, bd, out, out_size);                   // 6
}

// round 12
// speedup vs baseline: 1.6614x; 1.1050x over previous
#include <cuda_runtime.h>
#include <cuda_fp16.h>
#include <cstdint>

#define NN 200000
#define NF 400000
#define NE (3*NF)

#define NBLK 196          // scan blocks (196*1024 >= NN)
#define KH 256            // h1 width
#define BM 64
#define NTILES (NN / BM)  // 3125
#define ASTR 264          // As/W1s row stride (halves)
#define BSTR 136          // Bs row stride (halves)

// dynamic SMEM layout (halves)
#define W1S_OFF 0
#define AS_OFF  (16 * ASTR)                 // 4224
#define BS_OFF  (AS_OFF + 64 * ASTR)        // 21120
#define SM_HALVES (BS_OFF + 256 * BSTR)     // 55936
#define SM_TOTAL (SM_HALVES * 2)            // 111872 bytes -> 2 CTAs/SM

// -------- scratch (zero-initialized at module load; every replay restores) ----
__device__ int g_deg[NN];            // reset by k_layer2
__device__ float g_s1[3 * NN];       // reset by k_layer2
__device__ int g_flag[NBLK];         // reset by k_fill
__device__ float g_gsum[128];        // reset by k_final
__device__ int g_rowptr[NN + 1];
__device__ int g_cursor[NN];
__device__ int g_aggval[NBLK];
__device__ int g_incval[NBLK];
__device__ int g_colidx[NE];
__device__ __half g_t[(size_t)NN * 128];    // 51.2 MB (gathered)
__device__ __half g_u[(size_t)NN * 128];    // 51.2 MB (streamed)
__device__ __half g_Wc[256 * 256];          // [k][n]: fp16(W2l|W2r)

// ---- L1: face-parallel hist + pos aggregation + fp16 weight conversion -------
__global__ void k_hist(const int* __restrict__ face, const float* __restrict__ pos,
                       const float* __restrict__ W2l, const float* __restrict__ W2r) {
    int i = blockIdx.x * blockDim.x + threadIdx.x;
    if (i < 256 * 256) {
        int k = i >> 8, c = i & 255;
        float w = (c < 128) ? W2l[k * 128 + c] : W2r[k * 128 + (c - 128)];
        g_Wc[k * 256 + c] = __float2half_rn(w);
    }
    if (i >= NF) return;
    int v0 = face[i], v1 = face[NF + i], v2 = face[2 * NF + i];
    float p0x = pos[3 * v0 + 0], p0y = pos[3 * v0 + 1], p0z = pos[3 * v0 + 2];
    if (v0 != v1) {
        atomicAdd(&g_deg[v1], 1);
        atomicAdd(&g_s1[3 * v1 + 0], p0x);
        atomicAdd(&g_s1[3 * v1 + 1], p0y);
        atomicAdd(&g_s1[3 * v1 + 2], p0z);
    }
    if (v1 != v2) {
        atomicAdd(&g_deg[v2], 1);
        atomicAdd(&g_s1[3 * v2 + 0], pos[3 * v1 + 0]);
        atomicAdd(&g_s1[3 * v2 + 1], pos[3 * v1 + 1]);
        atomicAdd(&g_s1[3 * v2 + 2], pos[3 * v1 + 2]);
    }
    if (v0 != v2) {
        atomicAdd(&g_deg[v2], 1);
        atomicAdd(&g_s1[3 * v2 + 0], p0x);
        atomicAdd(&g_s1[3 * v2 + 1], p0y);
        atomicAdd(&g_s1[3 * v2 + 2], p0z);
    }
}

// ---- L2: single-pass decoupled-lookback scan (rowptr + cursor) ---------------
__global__ void k_scan() {
    __shared__ int s[1024];
    __shared__ int sprefix;
    int b = blockIdx.x;
    int tid = threadIdx.x;
    int i = b * 1024 + tid;
    int v = (i < NN) ? g_deg[i] : 0;
    s[tid] = v;
    __syncthreads();
    #pragma unroll
    for (int off = 1; off < 1024; off <<= 1) {
        int t = (tid >= off) ? s[tid - off] : 0;
        __syncthreads();
        s[tid] += t;
        __syncthreads();
    }
    int total = s[1023];
    if (tid == 0) {
        if (b == 0) {
            g_incval[0] = total;
            __threadfence();
            atomicExch(&g_flag[0], 2);
            sprefix = 0;
        } else {
            g_aggval[b] = total;
            __threadfence();
            atomicExch(&g_flag[b], 1);
            int prefix = 0;
            int j = b - 1;
            while (j >= 0) {
                int f;
                do { f = atomicAdd(&g_flag[j], 0); } while (f == 0);
                if (f == 2) { prefix += g_incval[j]; break; }
                prefix += g_aggval[j];
                j--;
            }
            g_incval[b] = prefix + total;
            __threadfence();
            atomicExch(&g_flag[b], 2);
            sprefix = prefix;
        }
    }
    __syncthreads();
    int p = sprefix;
    if (i < NN) {
        int r = p + s[tid] - v;   // exclusive
        g_rowptr[i] = r;
        g_cursor[i] = r;
    }
    if (b == NBLK - 1 && tid == 1023) g_rowptr[NN] = p + total;
}

// ---- L3: fill CSR (+ restore scan flags) --------------------------------------
__global__ void k_fill(const int* __restrict__ face) {
    int i = blockIdx.x * blockDim.x + threadIdx.x;
    if (i < NBLK) g_flag[i] = 0;            // restore invariant
    if (i >= NF) return;
    int v0 = face[i], v1 = face[NF + i], v2 = face[2 * NF + i];
    if (v0 != v1) g_colidx[atomicAdd(&g_cursor[v1], 1)] = v0;
    if (v1 != v2) g_colidx[atomicAdd(&g_cursor[v2], 1)] = v1;
    if (v0 != v2) g_colidx[atomicAdd(&g_cursor[v2], 1)] = v0;
}

// ---- L4 (PROFILED): persistent N-split fused GEMM -----------------------------
// Grid = 2*numSM. CTA owns N-half `half` (128 of 256 outputs), Wc-half + W1
// SMEM-resident; grid-strides over 3125 M-tiles. Per tile: phase 1 = one K=16
// mma builds h1 (64x256) into As; phase 2 = K=256 with zero global B traffic
// and zero syncs in the K loop.
__global__ void __launch_bounds__(256) k_gemm(
        const float* __restrict__ pos, const float* __restrict__ W1l,
        const float* __restrict__ W1r, const float* __restrict__ b1) {
    extern __shared__ __half sm[];
    __half* W1s = sm + W1S_OFF;   // [16][ASTR]
    __half* As  = sm + AS_OFF;    // [64][ASTR]
    __half* Bs  = sm + BS_OFF;    // [256][BSTR]  (Wc N-half, K-major)

    int tid = threadIdx.x;
    int warp = tid >> 5, lane = tid & 31;
    int wm = warp & 1;
    int wn4 = warp >> 1;          // 0..3 (phase-1: 64-col slices; phase-2: 32-col)
    int half = blockIdx.x & 1;
    int start = blockIdx.x >> 1;
    int stride = gridDim.x >> 1;

    // -------- one-time: W1 tile (16x256; rows 0-2 W1l, 3-5 W1r, 6 b1, 7-15 = 0)
    #pragma unroll
    for (int j = 0; j < 2; j++) {
        int idx = tid + 256 * j;
        int row = idx >> 5, cq = idx & 31;
        int c = cq * 8;
        float v[8];
        #pragma unroll
        for (int q = 0; q < 8; q++) {
            float w = 0.0f;
            if (row < 3)       w = W1l[row * 256 + c + q];
            else if (row < 6)  w = W1r[(row - 3) * 256 + c + q];
            else if (row == 6) w = b1[c + q];
            v[q] = w;
        }
        __half2 h0 = __floats2half2_rn(v[0], v[1]);
        __half2 h1 = __floats2half2_rn(v[2], v[3]);
        __half2 h2 = __floats2half2_rn(v[4], v[5]);
        __half2 h3 = __floats2half2_rn(v[6], v[7]);
        *(uint4*)(W1s + row * ASTR + c) = make_uint4(*(unsigned*)&h0, *(unsigned*)&h1,
                                                     *(unsigned*)&h2, *(unsigned*)&h3);
    }
    // -------- one-time: Wc N-half (256 x 128 fp16)
    #pragma unroll
    for (int j = 0; j < 16; j++) {
        int idx = tid + 256 * j;        // 4096 uint4
        int row = idx >> 4, cq = idx & 15;
        *(uint4*)(Bs + row * BSTR + cq * 8) =
            *(const uint4*)(g_Wc + (size_t)row * 256 + half * 128 + cq * 8);
    }

    __half* outbase = half ? g_u : g_t;

    for (int mt = start; mt < NTILES; mt += stride) {
        int bm = mt * BM;
        __syncthreads();   // prior tile's phase-2 reads of As complete

        // ---- A16: one row per node = [ax,ay,az,px,py,pz,1,0...] (NO reset here)
        if (tid < 64) {
            int node = bm + tid;
            int deg = g_deg[node];
            float inv = 1.0f / fmaxf((float)deg, 1.0f);
            float ax = g_s1[3 * node + 0] * inv;
            float ay = g_s1[3 * node + 1] * inv;
            float az = g_s1[3 * node + 2] * inv;
            float px = pos[3 * node + 0], py = pos[3 * node + 1], pz = pos[3 * node + 2];
            __half2 c01 = __floats2half2_rn(ax, ay);
            __half2 c23 = __floats2half2_rn(az, px);
            __half2 c45 = __floats2half2_rn(py, pz);
            __half2 c67 = __floats2half2_rn(1.0f, 0.0f);
            *(uint4*)(As + tid * ASTR + 0) = make_uint4(*(unsigned*)&c01, *(unsigned*)&c23,
                                                        *(unsigned*)&c45, *(unsigned*)&c67);
            *(uint4*)(As + tid * ASTR + 8) = make_uint4(0, 0, 0, 0);
        }
        __syncthreads();

        // ---- phase 1: K=16 mma -> h1 fragments (full 256 cols, 8 warps 2Mx4N)
        float acc[2][8][4];
        #pragma unroll
        for (int mi = 0; mi < 2; mi++)
            #pragma unroll
            for (int ni = 0; ni < 8; ni++)
                #pragma unroll
                for (int q = 0; q < 4; q++) acc[mi][ni][q] = 0.0f;
        {
            uint32_t a[2][4];
            #pragma unroll
            for (int mi = 0; mi < 2; mi++) {
                int r = wm * 32 + mi * 16 + (lane & 7) + 8 * ((lane >> 3) & 1);
                int cc = 8 * (lane >> 4);
                uint32_t addr = (uint32_t)__cvta_generic_to_shared(As + r * ASTR + cc);
                asm volatile("ldmatrix.sync.aligned.m8n8.x4.shared.b16 {%0,%1,%2,%3}, [%4];"
                             : "=r"(a[mi][0]), "=r"(a[mi][1]), "=r"(a[mi][2]), "=r"(a[mi][3])
                             : "r"(addr));
            }
            int rr = (lane & 7) + 8 * ((lane >> 3) & 1);
            #pragma unroll
            for (int np = 0; np < 4; np++) {
                int ncol = wn4 * 64 + np * 16 + 8 * (lane >> 4);
                uint32_t b[4];
                uint32_t baddr = (uint32_t)__cvta_generic_to_shared(W1s + rr * ASTR + ncol);
                asm volatile("ldmatrix.sync.aligned.m8n8.x4.trans.shared.b16 {%0,%1,%2,%3}, [%4];"
                             : "=r"(b[0]), "=r"(b[1]), "=r"(b[2]), "=r"(b[3])
                             : "r"(baddr));
                #pragma unroll
                for (int mi = 0; mi < 2; mi++) {
                    #pragma unroll
                    for (int h = 0; h < 2; h++) {
                        int ni = np * 2 + h;
                        asm volatile(
                            "mma.sync.aligned.m16n8k16.row.col.f32.f16.f16.f32 "
                            "{%0,%1,%2,%3},{%4,%5,%6,%7},{%8,%9},{%0,%1,%2,%3};"
                            : "+f"(acc[mi][ni][0]), "+f"(acc[mi][ni][1]),
                              "+f"(acc[mi][ni][2]), "+f"(acc[mi][ni][3])
                            : "r"(a[mi][0]), "r"(a[mi][1]), "r"(a[mi][2]), "r"(a[mi][3]),
                              "r"(b[2 * h]), "r"(b[2 * h + 1]));
                    }
                }
            }
        }
        __syncthreads();   // A16 reads complete before overwrite

        // relu + store h1 fragments into As (full 64 x 256)
        {
            int gid = lane >> 2, qid = lane & 3;
            #pragma unroll
            for (int mi = 0; mi < 2; mi++) {
                int r0 = wm * 32 + mi * 16 + gid;
                int r1 = r0 + 8;
                #pragma unroll
                for (int ni = 0; ni < 8; ni++) {
                    int col = wn4 * 64 + ni * 8 + qid * 2;
                    __half2 p0 = __floats2half2_rn(fmaxf(acc[mi][ni][0], 0.0f),
                                                   fmaxf(acc[mi][ni][1], 0.0f));
                    *(unsigned*)(As + r0 * ASTR + col) = *(unsigned*)&p0;
                    __half2 p1 = __floats2half2_rn(fmaxf(acc[mi][ni][2], 0.0f),
                                                   fmaxf(acc[mi][ni][3], 0.0f));
                    *(unsigned*)(As + r1 * ASTR + col) = *(unsigned*)&p1;
                }
            }
        }
        __syncthreads();

        // ---- phase 2: [t|u]-half = As @ Bs; K=256, all SMEM, NO syncs ----
        #pragma unroll
        for (int mi = 0; mi < 2; mi++)
            #pragma unroll
            for (int ni = 0; ni < 4; ni++)
                #pragma unroll
                for (int q = 0; q < 4; q++) acc[mi][ni][q] = 0.0f;

        #pragma unroll 4
        for (int k0 = 0; k0 < KH; k0 += 16) {
            uint32_t a[2][4];
            #pragma unroll
            for (int mi = 0; mi < 2; mi++) {
                int r = wm * 32 + mi * 16 + (lane & 7) + 8 * ((lane >> 3) & 1);
                int cc = k0 + 8 * (lane >> 4);
                uint32_t addr = (uint32_t)__cvta_generic_to_shared(As + r * ASTR + cc);
                asm volatile("ldmatrix.sync.aligned.m8n8.x4.shared.b16 {%0,%1,%2,%3}, [%4];"
                             : "=r"(a[mi][0]), "=r"(a[mi][1]), "=r"(a[mi][2]), "=r"(a[mi][3])
                             : "r"(addr));
            }
            int rr = k0 + (lane & 7) + 8 * ((lane >> 3) & 1);
            #pragma unroll
            for (int np = 0; np < 2; np++) {
                int ncol = wn4 * 32 + np * 16 + 8 * (lane >> 4);
                uint32_t b[4];
                uint32_t baddr = (uint32_t)__cvta_generic_to_shared(Bs + rr * BSTR + ncol);
                asm volatile("ldmatrix.sync.aligned.m8n8.x4.trans.shared.b16 {%0,%1,%2,%3}, [%4];"
                             : "=r"(b[0]), "=r"(b[1]), "=r"(b[2]), "=r"(b[3])
                             : "r"(baddr));
                #pragma unroll
                for (int mi = 0; mi < 2; mi++) {
                    #pragma unroll
                    for (int h = 0; h < 2; h++) {
                        int ni = np * 2 + h;
                        asm volatile(
                            "mma.sync.aligned.m16n8k16.row.col.f32.f16.f16.f32 "
                            "{%0,%1,%2,%3},{%4,%5,%6,%7},{%8,%9},{%0,%1,%2,%3};"
                            : "+f"(acc[mi][ni][0]), "+f"(acc[mi][ni][1]),
                              "+f"(acc[mi][ni][2]), "+f"(acc[mi][ni][3])
                            : "r"(a[mi][0]), "r"(a[mi][1]), "r"(a[mi][2]), "r"(a[mi][3]),
                              "r"(b[2 * h]), "r"(b[2 * h + 1]));
                    }
                }
            }
        }

        // epilogue: fp16 store to g_t (half 0) or g_u (half 1)
        {
            int gid = lane >> 2, qid = lane & 3;
            #pragma unroll
            for (int mi = 0; mi < 2; mi++) {
                int r0 = bm + wm * 32 + mi * 16 + gid;
                int r1 = r0 + 8;
                #pragma unroll
                for (int ni = 0; ni < 4; ni++) {
                    int col = wn4 * 32 + ni * 8 + qid * 2;
                    __half2 p0 = __floats2half2_rn(acc[0 + (mi==1)][ni][0], acc[mi][ni][1]);
                    p0 = __floats2half2_rn(acc[mi][ni][0], acc[mi][ni][1]);
                    *(unsigned*)(outbase + (size_t)r0 * 128 + col) = *(unsigned*)&p0;
                    __half2 p1 = __floats2half2_rn(acc[mi][ni][2], acc[mi][ni][3]);
                    *(unsigned*)(outbase + (size_t)r1 * 128 + col) = *(unsigned*)&p1;
                }
            }
        }
    }
}

// ---- L5: layer-2 aggregate + relu + mean-pool (+ restore deg/s1) --------------
__global__ void k_layer2(const float* __restrict__ b2) {
    __shared__ float gsh[128];
    if (threadIdx.x < 128) gsh[threadIdx.x] = 0.0f;
    __syncthreads();

    int wid = threadIdx.x >> 5, lane = threadIdx.x & 31;
    int gwarp = blockIdx.x * (blockDim.x >> 5) + wid;
    int nwarps = gridDim.x * (blockDim.x >> 5);
    float4 bl = ((const float4*)b2)[lane];

    float a0 = 0.f, a1 = 0.f, a2 = 0.f, a3 = 0.f;
    for (int node = gwarp; node < NN; node += nwarps) {
        int beg = g_rowptr[node], end = g_rowptr[node + 1];
        if (lane == 0) {                 // restore invariants (gemm done reading)
            g_deg[node] = 0;
            g_s1[3 * node + 0] = 0.0f;
            g_s1[3 * node + 1] = 0.0f;
            g_s1[3 * node + 2] = 0.0f;
        }
        float s0 = 0.f, s1 = 0.f, s2 = 0.f, s3 = 0.f;
        #pragma unroll 4
        for (int j = beg; j < end; j++) {
            int src = g_colidx[j];
            uint2 tv = ((const uint2*)(g_t + (size_t)src * 128))[lane];
            float2 t01 = __half22float2(*(__half2*)&tv.x);
            float2 t23 = __half22float2(*(__half2*)&tv.y);
            s0 += t01.x; s1 += t01.y;
            s2 += t23.x; s3 += t23.y;
        }
        float inv = 1.0f / fmaxf((float)(end - beg), 1.0f);
        uint2 uv = ((const uint2*)(g_u + (size_t)node * 128))[lane];
        float2 u01 = __half22float2(*(__half2*)&uv.x);
        float2 u23 = __half22float2(*(__half2*)&uv.y);
        a0 += fmaxf(s0 * inv + u01.x + bl.x, 0.0f);
        a1 += fmaxf(s1 * inv + u01.y + bl.y, 0.0f);
        a2 += fmaxf(s2 * inv + u23.x + bl.z, 0.0f);
        a3 += fmaxf(s3 * inv + u23.y + bl.w, 0.0f);
    }
    atomicAdd(&gsh[lane * 4 + 0], a0);
    atomicAdd(&gsh[lane * 4 + 1], a1);
    atomicAdd(&gsh[lane * 4 + 2], a2);
    atomicAdd(&gsh[lane * 4 + 3], a3);
    __syncthreads();
    if (threadIdx.x < 128) atomicAdd(&g_gsum[threadIdx.x], gsh[threadIdx.x]);
}

// ---- L6: decoder + softmax + argmax (+ restore gsum) ---------------------------
__global__ void k_final(const float* __restrict__ Wd, const float* __restrict__ bd,
                        float* __restrict__ out, int out_size) {
    if (threadIdx.x != 0 || blockIdx.x != 0) return;
    float g[128];
    for (int c = 0; c < 128; c++) {
        g[c] = g_gsum[c] * (1.0f / (float)NN);
        g_gsum[c] = 0.0f;   // restore invariant
    }
    float lg[10];
    for (int j = 0; j < 10; j++) lg[j] = bd[j];
    for (int c = 0; c < 128; c++) {
        float gv = g[c];
        for (int j = 0; j < 10; j++) lg[j] += gv * Wd[c * 10 + j];
    }
    float m = lg[0];
    for (int j = 1; j < 10; j++) m = fmaxf(m, lg[j]);
    float e[10], s = 0.0f;
    for (int j = 0; j < 10; j++) { e[j] = expf(lg[j] - m); s += e[j]; }
    float invs = 1.0f / s;
    int am = 0;
    float best = -1.0f;
    for (int j = 0; j < 10; j++) {
        float p = e[j] * invs;
        if (j < out_size) out[j] = p;
        if (p > best) { best = p; am = j; }
    }
    for (int i = 10; i < out_size; i++) out[i] = (float)am;
}

// ---------------- launch --------------------------------------------------------
extern "C" void kernel_launch(void* const* d_in, const int* in_sizes, int n_in,
                              void* d_out, int out_size) {
    const float* pos = (const float*)d_in[0];
    const int*   face = (const int*)d_in[1];
    const float* W1l = (const float*)d_in[2];
    const float* W1r = (const float*)d_in[3];
    const float* b1  = (const float*)d_in[4];
    const float* W2l = (const float*)d_in[5];
    const float* W2r = (const float*)d_in[6];
    const float* b2  = (const float*)d_in[7];
    const float* Wd  = (const float*)d_in[8];
    const float* bd  = (const float*)d_in[9];
    float* out = (float*)d_out;

    int dev = 0, nsm = 148;
    cudaGetDevice(&dev);
    cudaDeviceGetAttribute(&nsm, cudaDevAttrMultiProcessorCount, dev);
    cudaFuncSetAttribute(k_gemm, cudaFuncAttributeMaxDynamicSharedMemorySize, SM_TOTAL);

    k_hist   <<<(NF + 255) / 256, 256>>>(face, pos, W2l, W2r);     // 1
    k_scan   <<<NBLK, 1024>>>();                                   // 2
    k_fill   <<<(NF + 255) / 256, 256>>>(face);                    // 3
    k_gemm   <<<2 * nsm, 256, SM_TOTAL>>>(pos, W1l, W1r, b1);      // 4  <- profiled
    k_layer2 <<<1184, 256>>>(b2);                                  // 5
    k_final  <<<1, 32>>>(Wd, bd, out, out_size);                   // 6
}

// round 13
// speedup vs baseline: 1.7098x; 1.0292x over previous
#include <cuda_runtime.h>
#include <cuda_fp16.h>
#include <cuda_fp8.h>
#include <cstdint>

#define NN 200000
#define NF 400000
#define NE (3*NF)

#define NBLK 196          // scan blocks (196*1024 >= NN)
#define KH 256            // h1 width
#define BM 64
#define NTILES (NN / BM)  // 3125
#define ASTR 264          // As/W1s row stride (halves)
#define BSTR 136          // Bs row stride (halves)

// dynamic SMEM layout (halves)
#define W1S_OFF 0
#define AS_OFF  (16 * ASTR)                 // 4224
#define BS_OFF  (AS_OFF + 64 * ASTR)        // 21120
#define SM_HALVES (BS_OFF + 256 * BSTR)     // 55936
#define SM_TOTAL (SM_HALVES * 2)            // 111872 bytes -> 2 CTAs/SM

// -------- scratch (zero-initialized at module load; every replay restores) ----
__device__ __half2 g_s1h[2 * NN];    // [2n]=(sx,sy), [2n+1]=(sz,count); reset by k_layer2
__device__ int g_flag[NBLK];         // reset by k_fill
__device__ float g_gsum[128];        // reset by k_final
__device__ int g_rowptr[NN + 1];
__device__ int g_cursor[NN];
__device__ int g_aggval[NBLK];
__device__ int g_incval[NBLK];
__device__ int g_colidx[NE];
__device__ unsigned char g_t8[(size_t)NN * 128];  // 25.6 MB fp8 e4m3 (gathered 6x)
__device__ __half g_u[(size_t)NN * 128];          // 51.2 MB fp16 (streamed once)
__device__ __half g_Wc[256 * 256];                // [k][n]: fp16(W2l|W2r)

// ---- L1: face-parallel hist (half2 atomics) + fp16 weight conversion ---------
__global__ void k_hist(const int* __restrict__ face, const float* __restrict__ pos,
                       const float* __restrict__ W2l, const float* __restrict__ W2r) {
    int i = blockIdx.x * blockDim.x + threadIdx.x;
    if (i < 256 * 256) {
        int k = i >> 8, c = i & 255;
        float w = (c < 128) ? W2l[k * 128 + c] : W2r[k * 128 + (c - 128)];
        g_Wc[k * 256 + c] = __float2half_rn(w);
    }
    if (i >= NF) return;
    int v0 = face[i], v1 = face[NF + i], v2 = face[2 * NF + i];
    float p0x = pos[3 * v0 + 0], p0y = pos[3 * v0 + 1], p0z = pos[3 * v0 + 2];
    __half2 p0xy = __floats2half2_rn(p0x, p0y);
    __half2 p0zc = __floats2half2_rn(p0z, 1.0f);
    if (v0 != v1) {
        atomicAdd(&g_s1h[2 * v1 + 0], p0xy);
        atomicAdd(&g_s1h[2 * v1 + 1], p0zc);
    }
    if (v1 != v2) {
        atomicAdd(&g_s1h[2 * v2 + 0], __floats2half2_rn(pos[3 * v1 + 0], pos[3 * v1 + 1]));
        atomicAdd(&g_s1h[2 * v2 + 1], __floats2half2_rn(pos[3 * v1 + 2], 1.0f));
    }
    if (v0 != v2) {
        atomicAdd(&g_s1h[2 * v2 + 0], p0xy);
        atomicAdd(&g_s1h[2 * v2 + 1], p0zc);
    }
}

// ---- L2: single-pass decoupled-lookback scan (rowptr + cursor) ---------------
__global__ void k_scan() {
    __shared__ int s[1024];
    __shared__ int sprefix;
    int b = blockIdx.x;
    int tid = threadIdx.x;
    int i = b * 1024 + tid;
    int v = 0;
    if (i < NN) {
        __half2 zc = g_s1h[2 * i + 1];
        v = (int)(__half2float(__high2half(zc)) + 0.5f);
    }
    s[tid] = v;
    __syncthreads();
    #pragma unroll
    for (int off = 1; off < 1024; off <<= 1) {
        int t = (tid >= off) ? s[tid - off] : 0;
        __syncthreads();
        s[tid] += t;
        __syncthreads();
    }
    int total = s[1023];
    if (tid == 0) {
        if (b == 0) {
            g_incval[0] = total;
            __threadfence();
            atomicExch(&g_flag[0], 2);
            sprefix = 0;
        } else {
            g_aggval[b] = total;
            __threadfence();
            atomicExch(&g_flag[b], 1);
            int prefix = 0;
            int j = b - 1;
            while (j >= 0) {
                int f;
                do { f = atomicAdd(&g_flag[j], 0); } while (f == 0);
                if (f == 2) { prefix += g_incval[j]; break; }
                prefix += g_aggval[j];
                j--;
            }
            g_incval[b] = prefix + total;
            __threadfence();
            atomicExch(&g_flag[b], 2);
            sprefix = prefix;
        }
    }
    __syncthreads();
    int p = sprefix;
    if (i < NN) {
        int r = p + s[tid] - v;   // exclusive
        g_rowptr[i] = r;
        g_cursor[i] = r;
    }
    if (b == NBLK - 1 && tid == 1023) g_rowptr[NN] = p + total;
}

// ---- L3: fill CSR (+ restore scan flags) --------------------------------------
__global__ void k_fill(const int* __restrict__ face) {
    int i = blockIdx.x * blockDim.x + threadIdx.x;
    if (i < NBLK) g_flag[i] = 0;            // restore invariant
    if (i >= NF) return;
    int v0 = face[i], v1 = face[NF + i], v2 = face[2 * NF + i];
    if (v0 != v1) g_colidx[atomicAdd(&g_cursor[v1], 1)] = v0;
    if (v1 != v2) g_colidx[atomicAdd(&g_cursor[v2], 1)] = v1;
    if (v0 != v2) g_colidx[atomicAdd(&g_cursor[v2], 1)] = v0;
}

// ---- L4 (PROFILED): persistent N-split fused GEMM -----------------------------
// CTA owns N-half (128 of 256 outputs); Wc-half + W1 SMEM-resident; grid-strides
// over 3125 M-tiles. Phase 1: K=16 mma builds h1 (64x256) into As. Phase 2:
// K=256, zero global B traffic, zero syncs in K loop. Output: t -> fp8, u -> fp16.
__global__ void __launch_bounds__(256) k_gemm(
        const float* __restrict__ pos, const float* __restrict__ W1l,
        const float* __restrict__ W1r, const float* __restrict__ b1) {
    extern __shared__ __half sm[];
    __half* W1s = sm + W1S_OFF;   // [16][ASTR]
    __half* As  = sm + AS_OFF;    // [64][ASTR]
    __half* Bs  = sm + BS_OFF;    // [256][BSTR]  (Wc N-half, K-major)

    int tid = threadIdx.x;
    int warp = tid >> 5, lane = tid & 31;
    int wm = warp & 1;
    int wn4 = warp >> 1;          // 0..3
    int half = blockIdx.x & 1;
    int start = blockIdx.x >> 1;
    int stride = gridDim.x >> 1;

    // one-time: W1 tile (16x256; rows 0-2 W1l, 3-5 W1r, 6 b1, 7-15 = 0)
    #pragma unroll
    for (int j = 0; j < 2; j++) {
        int idx = tid + 256 * j;
        int row = idx >> 5, cq = idx & 31;
        int c = cq * 8;
        float v[8];
        #pragma unroll
        for (int q = 0; q < 8; q++) {
            float w = 0.0f;
            if (row < 3)       w = W1l[row * 256 + c + q];
            else if (row < 6)  w = W1r[(row - 3) * 256 + c + q];
            else if (row == 6) w = b1[c + q];
            v[q] = w;
        }
        __half2 h0 = __floats2half2_rn(v[0], v[1]);
        __half2 h1 = __floats2half2_rn(v[2], v[3]);
        __half2 h2 = __floats2half2_rn(v[4], v[5]);
        __half2 h3 = __floats2half2_rn(v[6], v[7]);
        *(uint4*)(W1s + row * ASTR + c) = make_uint4(*(unsigned*)&h0, *(unsigned*)&h1,
                                                     *(unsigned*)&h2, *(unsigned*)&h3);
    }
    // one-time: Wc N-half (256 x 128 fp16)
    #pragma unroll
    for (int j = 0; j < 16; j++) {
        int idx = tid + 256 * j;
        int row = idx >> 4, cq = idx & 15;
        *(uint4*)(Bs + row * BSTR + cq * 8) =
            *(const uint4*)(g_Wc + (size_t)row * 256 + half * 128 + cq * 8);
    }

    for (int mt = start; mt < NTILES; mt += stride) {
        int bm = mt * BM;
        __syncthreads();   // prior tile's phase-2 reads of As complete

        if (tid < 64) {
            int node = bm + tid;
            __half2 xy = g_s1h[2 * node + 0];
            __half2 zc = g_s1h[2 * node + 1];
            float deg = __half2float(__high2half(zc));
            float inv = 1.0f / fmaxf(deg, 1.0f);
            float ax = __half2float(__low2half(xy)) * inv;
            float ay = __half2float(__high2half(xy)) * inv;
            float az = __half2float(__low2half(zc)) * inv;
            float px = pos[3 * node + 0], py = pos[3 * node + 1], pz = pos[3 * node + 2];
            __half2 c01 = __floats2half2_rn(ax, ay);
            __half2 c23 = __floats2half2_rn(az, px);
            __half2 c45 = __floats2half2_rn(py, pz);
            __half2 c67 = __floats2half2_rn(1.0f, 0.0f);
            *(uint4*)(As + tid * ASTR + 0) = make_uint4(*(unsigned*)&c01, *(unsigned*)&c23,
                                                        *(unsigned*)&c45, *(unsigned*)&c67);
            *(uint4*)(As + tid * ASTR + 8) = make_uint4(0, 0, 0, 0);
        }
        __syncthreads();

        // phase 1: K=16 mma -> h1 fragments (full 256 cols)
        float acc[2][8][4];
        #pragma unroll
        for (int mi = 0; mi < 2; mi++)
            #pragma unroll
            for (int ni = 0; ni < 8; ni++)
                #pragma unroll
                for (int q = 0; q < 4; q++) acc[mi][ni][q] = 0.0f;
        {
            uint32_t a[2][4];
            #pragma unroll
            for (int mi = 0; mi < 2; mi++) {
                int r = wm * 32 + mi * 16 + (lane & 7) + 8 * ((lane >> 3) & 1);
                int cc = 8 * (lane >> 4);
                uint32_t addr = (uint32_t)__cvta_generic_to_shared(As + r * ASTR + cc);
                asm volatile("ldmatrix.sync.aligned.m8n8.x4.shared.b16 {%0,%1,%2,%3}, [%4];"
                             : "=r"(a[mi][0]), "=r"(a[mi][1]), "=r"(a[mi][2]), "=r"(a[mi][3])
                             : "r"(addr));
            }
            int rr = (lane & 7) + 8 * ((lane >> 3) & 1);
            #pragma unroll
            for (int np = 0; np < 4; np++) {
                int ncol = wn4 * 64 + np * 16 + 8 * (lane >> 4);
                uint32_t b[4];
                uint32_t baddr = (uint32_t)__cvta_generic_to_shared(W1s + rr * ASTR + ncol);
                asm volatile("ldmatrix.sync.aligned.m8n8.x4.trans.shared.b16 {%0,%1,%2,%3}, [%4];"
                             : "=r"(b[0]), "=r"(b[1]), "=r"(b[2]), "=r"(b[3])
                             : "r"(baddr));
                #pragma unroll
                for (int mi = 0; mi < 2; mi++) {
                    #pragma unroll
                    for (int h = 0; h < 2; h++) {
                        int ni = np * 2 + h;
                        asm volatile(
                            "mma.sync.aligned.m16n8k16.row.col.f32.f16.f16.f32 "
                            "{%0,%1,%2,%3},{%4,%5,%6,%7},{%8,%9},{%0,%1,%2,%3};"
                            : "+f"(acc[mi][ni][0]), "+f"(acc[mi][ni][1]),
                              "+f"(acc[mi][ni][2]), "+f"(acc[mi][ni][3])
                            : "r"(a[mi][0]), "r"(a[mi][1]), "r"(a[mi][2]), "r"(a[mi][3]),
                              "r"(b[2 * h]), "r"(b[2 * h + 1]));
                    }
                }
            }
        }
        __syncthreads();

        // relu + store h1 fragments into As
        {
            int gid = lane >> 2, qid = lane & 3;
            #pragma unroll
            for (int mi = 0; mi < 2; mi++) {
                int r0 = wm * 32 + mi * 16 + gid;
                int r1 = r0 + 8;
                #pragma unroll
                for (int ni = 0; ni < 8; ni++) {
                    int col = wn4 * 64 + ni * 8 + qid * 2;
                    __half2 p0 = __floats2half2_rn(fmaxf(acc[mi][ni][0], 0.0f),
                                                   fmaxf(acc[mi][ni][1], 0.0f));
                    *(unsigned*)(As + r0 * ASTR + col) = *(unsigned*)&p0;
                    __half2 p1 = __floats2half2_rn(fmaxf(acc[mi][ni][2], 0.0f),
                                                   fmaxf(acc[mi][ni][3], 0.0f));
                    *(unsigned*)(As + r1 * ASTR + col) = *(unsigned*)&p1;
                }
            }
        }
        __syncthreads();

        // phase 2: [t|u]-half = As @ Bs; K=256, all SMEM, no syncs
        #pragma unroll
        for (int mi = 0; mi < 2; mi++)
            #pragma unroll
            for (int ni = 0; ni < 4; ni++)
                #pragma unroll
                for (int q = 0; q < 4; q++) acc[mi][ni][q] = 0.0f;

        #pragma unroll 4
        for (int k0 = 0; k0 < KH; k0 += 16) {
            uint32_t a[2][4];
            #pragma unroll
            for (int mi = 0; mi < 2; mi++) {
                int r = wm * 32 + mi * 16 + (lane & 7) + 8 * ((lane >> 3) & 1);
                int cc = k0 + 8 * (lane >> 4);
                uint32_t addr = (uint32_t)__cvta_generic_to_shared(As + r * ASTR + cc);
                asm volatile("ldmatrix.sync.aligned.m8n8.x4.shared.b16 {%0,%1,%2,%3}, [%4];"
                             : "=r"(a[mi][0]), "=r"(a[mi][1]), "=r"(a[mi][2]), "=r"(a[mi][3])
                             : "r"(addr));
            }
            int rr = k0 + (lane & 7) + 8 * ((lane >> 3) & 1);
            #pragma unroll
            for (int np = 0; np < 2; np++) {
                int ncol = wn4 * 32 + np * 16 + 8 * (lane >> 4);
                uint32_t b[4];
                uint32_t baddr = (uint32_t)__cvta_generic_to_shared(Bs + rr * BSTR + ncol);
                asm volatile("ldmatrix.sync.aligned.m8n8.x4.trans.shared.b16 {%0,%1,%2,%3}, [%4];"
                             : "=r"(b[0]), "=r"(b[1]), "=r"(b[2]), "=r"(b[3])
                             : "r"(baddr));
                #pragma unroll
                for (int mi = 0; mi < 2; mi++) {
                    #pragma unroll
                    for (int h = 0; h < 2; h++) {
                        int ni = np * 2 + h;
                        asm volatile(
                            "mma.sync.aligned.m16n8k16.row.col.f32.f16.f16.f32 "
                            "{%0,%1,%2,%3},{%4,%5,%6,%7},{%8,%9},{%0,%1,%2,%3};"
                            : "+f"(acc[mi][ni][0]), "+f"(acc[mi][ni][1]),
                              "+f"(acc[mi][ni][2]), "+f"(acc[mi][ni][3])
                            : "r"(a[mi][0]), "r"(a[mi][1]), "r"(a[mi][2]), "r"(a[mi][3]),
                              "r"(b[2 * h]), "r"(b[2 * h + 1]));
                    }
                }
            }
        }

        // epilogue: half 0 -> g_t8 (fp8 e4m3), half 1 -> g_u (fp16)
        {
            int gid = lane >> 2, qid = lane & 3;
            #pragma unroll
            for (int mi = 0; mi < 2; mi++) {
                int r0 = bm + wm * 32 + mi * 16 + gid;
                int r1 = r0 + 8;
                #pragma unroll
                for (int ni = 0; ni < 4; ni++) {
                    int col = wn4 * 32 + ni * 8 + qid * 2;
                    if (half == 0) {
                        __nv_fp8x2_storage_t q0 = __nv_cvt_float2_to_fp8x2(
                            make_float2(acc[mi][ni][0], acc[mi][ni][1]),
                            __NV_SATFINITE, __NV_E4M3);
                        *(unsigned short*)(g_t8 + (size_t)r0 * 128 + col) = q0;
                        __nv_fp8x2_storage_t q1 = __nv_cvt_float2_to_fp8x2(
                            make_float2(acc[mi][ni][2], acc[mi][ni][3]),
                            __NV_SATFINITE, __NV_E4M3);
                        *(unsigned short*)(g_t8 + (size_t)r1 * 128 + col) = q1;
                    } else {
                        __half2 p0 = __floats2half2_rn(acc[mi][ni][0], acc[mi][ni][1]);
                        *(unsigned*)(g_u + (size_t)r0 * 128 + col) = *(unsigned*)&p0;
                        __half2 p1 = __floats2half2_rn(acc[mi][ni][2], acc[mi][ni][3]);
                        *(unsigned*)(g_u + (size_t)r1 * 128 + col) = *(unsigned*)&p1;
                    }
                }
            }
        }
    }
}

// ---- L5: layer-2 aggregate (fp8 gather) + relu + mean-pool (+ restore s1h) ----
__global__ void k_layer2(const float* __restrict__ b2) {
    __shared__ float gsh[128];
    if (threadIdx.x < 128) gsh[threadIdx.x] = 0.0f;
    __syncthreads();

    int wid = threadIdx.x >> 5, lane = threadIdx.x & 31;
    int gwarp = blockIdx.x * (blockDim.x >> 5) + wid;
    int nwarps = gridDim.x * (blockDim.x >> 5);
    float4 bl = ((const float4*)b2)[lane];

    float a0 = 0.f, a1 = 0.f, a2 = 0.f, a3 = 0.f;
    for (int node = gwarp; node < NN; node += nwarps) {
        int beg = g_rowptr[node], end = g_rowptr[node + 1];
        if (lane == 0) {                 // restore invariants (gemm done reading)
            g_s1h[2 * node + 0] = __floats2half2_rn(0.0f, 0.0f);
            g_s1h[2 * node + 1] = __floats2half2_rn(0.0f, 0.0f);
        }
        float s0 = 0.f, s1 = 0.f, s2 = 0.f, s3 = 0.f;
        #pragma unroll 4
        for (int j = beg; j < end; j++) {
            int src = g_colidx[j];
            unsigned tv = *(const unsigned*)(g_t8 + (size_t)src * 128 + lane * 4);
            __half2_raw r01 = __nv_cvt_fp8x2_to_halfraw2(
                (__nv_fp8x2_storage_t)(tv & 0xFFFFu), __NV_E4M3);
            __half2_raw r23 = __nv_cvt_fp8x2_to_halfraw2(
                (__nv_fp8x2_storage_t)(tv >> 16), __NV_E4M3);
            float2 t01 = __half22float2(*(__half2*)&r01);
            float2 t23 = __half22float2(*(__half2*)&r23);
            s0 += t01.x; s1 += t01.y;
            s2 += t23.x; s3 += t23.y;
        }
        float inv = 1.0f / fmaxf((float)(end - beg), 1.0f);
        uint2 uv = ((const uint2*)(g_u + (size_t)node * 128))[lane];
        float2 u01 = __half22float2(*(__half2*)&uv.x);
        float2 u23 = __half22float2(*(__half2*)&uv.y);
        a0 += fmaxf(s0 * inv + u01.x + bl.x, 0.0f);
        a1 += fmaxf(s1 * inv + u01.y + bl.y, 0.0f);
        a2 += fmaxf(s2 * inv + u23.x + bl.z, 0.0f);
        a3 += fmaxf(s3 * inv + u23.y + bl.w, 0.0f);
    }
    atomicAdd(&gsh[lane * 4 + 0], a0);
    atomicAdd(&gsh[lane * 4 + 1], a1);
    atomicAdd(&gsh[lane * 4 + 2], a2);
    atomicAdd(&gsh[lane * 4 + 3], a3);
    __syncthreads();
    if (threadIdx.x < 128) atomicAdd(&g_gsum[threadIdx.x], gsh[threadIdx.x]);
}

// ---- L6: decoder + softmax + argmax (+ restore gsum) ---------------------------
__global__ void k_final(const float* __restrict__ Wd, const float* __restrict__ bd,
                        float* __restrict__ out, int out_size) {
    if (threadIdx.x != 0 || blockIdx.x != 0) return;
    float g[128];
    for (int c = 0; c < 128; c++) {
        g[c] = g_gsum[c] * (1.0f / (float)NN);
        g_gsum[c] = 0.0f;   // restore invariant
    }
    float lg[10];
    for (int j = 0; j < 10; j++) lg[j] = bd[j];
    for (int c = 0; c < 128; c++) {
        float gv = g[c];
        for (int j = 0; j < 10; j++) lg[j] += gv * Wd[c * 10 + j];
    }
    float m = lg[0];
    for (int j = 1; j < 10; j++) m = fmaxf(m, lg[j]);
    float e[10], s = 0.0f;
    for (int j = 0; j < 10; j++) { e[j] = expf(lg[j] - m); s += e[j]; }
    float invs = 1.0f / s;
    int am = 0;
    float best = -1.0f;
    for (int j = 0; j < 10; j++) {
        float p = e[j] * invs;
        if (j < out_size) out[j] = p;
        if (p > best) { best = p; am = j; }
    }
    for (int i = 10; i < out_size; i++) out[i] = (float)am;
}

// ---------------- launch --------------------------------------------------------
extern "C" void kernel_launch(void* const* d_in, const int* in_sizes, int n_in,
                              void* d_out, int out_size) {
    const float* pos = (const float*)d_in[0];
    const int*   face = (const int*)d_in[1];
    const float* W1l = (const float*)d_in[2];
    const float* W1r = (const float*)d_in[3];
    const float* b1  = (const float*)d_in[4];
    const float* W2l = (const float*)d_in[5];
    const float* W2r = (const float*)d_in[6];
    const float* b2  = (const float*)d_in[7];
    const float* Wd  = (const float*)d_in[8];
    const float* bd  = (const float*)d_in[9];
    float* out = (float*)d_out;

    int dev = 0, nsm = 148;
    cudaGetDevice(&dev);
    cudaDeviceGetAttribute(&nsm, cudaDevAttrMultiProcessorCount, dev);
    cudaFuncSetAttribute(k_gemm, cudaFuncAttributeMaxDynamicSharedMemorySize, SM_TOTAL);

    k_hist   <<<(NF + 255) / 256, 256>>>(face, pos, W2l, W2r);     // 1
    k_scan   <<<NBLK, 1024>>>();                                   // 2
    k_fill   <<<(NF + 255) / 256, 256>>>(face);                    // 3
    k_gemm   <<<2 * nsm, 256, SM_TOTAL>>>(pos, W1l, W1r, b1);      // 4  <- profiled
    k_layer2 <<<1184, 256>>>(b2);                                  // 5
    k_final  <<<1, 32>>>(Wd, bd, out, out_size);                   // 6
}

// round 14
// speedup vs baseline: 1.7185x; 1.0051x over previous
#include <cuda_runtime.h>
#include <cuda_fp16.h>
#include <cuda_fp8.h>
#include <cstdint>

#define NN 200000
#define NF 400000
#define NE (3*NF)

#define NBLK 196          // scan blocks (196*1024 >= NN)
#define KH 256            // h1 width
#define BM 64
#define NTILES (NN / BM)  // 3125
#define ASTR 264          // row stride (halves) for all SMEM tiles

// dynamic SMEM layout (halves)
#define W1S_OFF 0
#define AS_OFF  (16 * ASTR)                 // 4224
#define BS_OFF  (AS_OFF + 64 * ASTR)        // 21120
#define SM_HALVES (BS_OFF + 256 * ASTR)     // 88704
#define SM_TOTAL (SM_HALVES * 2)            // 177408 bytes -> 1 CTA/SM

// -------- scratch (zero-initialized at module load; every replay restores) ----
__device__ __half2 g_s1h[2 * NN];    // [2n]=(sx,sy), [2n+1]=(sz,count); reset by k_layer2
__device__ int g_flag[NBLK];         // reset by k_fill
__device__ float g_gsum[128];        // reset by k_final
__device__ int g_rowptr[NN + 1];
__device__ int g_cursor[NN];
__device__ int g_aggval[NBLK];
__device__ int g_incval[NBLK];
__device__ int g_colidx[NE];
__device__ unsigned char g_t8[(size_t)NN * 128];  // 25.6 MB fp8 e4m3 (gathered 6x)
__device__ __half g_u[(size_t)NN * 128];          // 51.2 MB fp16 (streamed once)
__device__ __half g_Wc[256 * 256];                // [k][n]: fp16(W2l|W2r)

// ---- L1: face-parallel hist (half2 atomics) + fp16 weight conversion ---------
__global__ void k_hist(const int* __restrict__ face, const float* __restrict__ pos,
                       const float* __restrict__ W2l, const float* __restrict__ W2r) {
    int i = blockIdx.x * blockDim.x + threadIdx.x;
    if (i < 256 * 256) {
        int k = i >> 8, c = i & 255;
        float w = (c < 128) ? W2l[k * 128 + c] : W2r[k * 128 + (c - 128)];
        g_Wc[k * 256 + c] = __float2half_rn(w);
    }
    if (i >= NF) return;
    int v0 = face[i], v1 = face[NF + i], v2 = face[2 * NF + i];
    float p0x = pos[3 * v0 + 0], p0y = pos[3 * v0 + 1], p0z = pos[3 * v0 + 2];
    __half2 p0xy = __floats2half2_rn(p0x, p0y);
    __half2 p0zc = __floats2half2_rn(p0z, 1.0f);
    if (v0 != v1) {
        atomicAdd(&g_s1h[2 * v1 + 0], p0xy);
        atomicAdd(&g_s1h[2 * v1 + 1], p0zc);
    }
    if (v1 != v2) {
        atomicAdd(&g_s1h[2 * v2 + 0], __floats2half2_rn(pos[3 * v1 + 0], pos[3 * v1 + 1]));
        atomicAdd(&g_s1h[2 * v2 + 1], __floats2half2_rn(pos[3 * v1 + 2], 1.0f));
    }
    if (v0 != v2) {
        atomicAdd(&g_s1h[2 * v2 + 0], p0xy);
        atomicAdd(&g_s1h[2 * v2 + 1], p0zc);
    }
}

// ---- L2: single-pass decoupled-lookback scan (rowptr + cursor) ---------------
__global__ void k_scan() {
    __shared__ int s[1024];
    __shared__ int sprefix;
    int b = blockIdx.x;
    int tid = threadIdx.x;
    int i = b * 1024 + tid;
    int v = 0;
    if (i < NN) {
        __half2 zc = g_s1h[2 * i + 1];
        v = (int)(__half2float(__high2half(zc)) + 0.5f);
    }
    s[tid] = v;
    __syncthreads();
    #pragma unroll
    for (int off = 1; off < 1024; off <<= 1) {
        int t = (tid >= off) ? s[tid - off] : 0;
        __syncthreads();
        s[tid] += t;
        __syncthreads();
    }
    int total = s[1023];
    if (tid == 0) {
        if (b == 0) {
            g_incval[0] = total;
            __threadfence();
            atomicExch(&g_flag[0], 2);
            sprefix = 0;
        } else {
            g_aggval[b] = total;
            __threadfence();
            atomicExch(&g_flag[b], 1);
            int prefix = 0;
            int j = b - 1;
            while (j >= 0) {
                int f;
                do { f = atomicAdd(&g_flag[j], 0); } while (f == 0);
                if (f == 2) { prefix += g_incval[j]; break; }
                prefix += g_aggval[j];
                j--;
            }
            g_incval[b] = prefix + total;
            __threadfence();
            atomicExch(&g_flag[b], 2);
            sprefix = prefix;
        }
    }
    __syncthreads();
    int p = sprefix;
    if (i < NN) {
        int r = p + s[tid] - v;   // exclusive
        g_rowptr[i] = r;
        g_cursor[i] = r;
    }
    if (b == NBLK - 1 && tid == 1023) g_rowptr[NN] = p + total;
}

// ---- L3: fill CSR (+ restore scan flags) --------------------------------------
__global__ void k_fill(const int* __restrict__ face) {
    int i = blockIdx.x * blockDim.x + threadIdx.x;
    if (i < NBLK) g_flag[i] = 0;            // restore invariant
    if (i >= NF) return;
    int v0 = face[i], v1 = face[NF + i], v2 = face[2 * NF + i];
    if (v0 != v1) g_colidx[atomicAdd(&g_cursor[v1], 1)] = v0;
    if (v1 != v2) g_colidx[atomicAdd(&g_cursor[v2], 1)] = v1;
    if (v0 != v2) g_colidx[atomicAdd(&g_cursor[v2], 1)] = v0;
}

// ---- L4 (PROFILED): persistent full-N fused GEMM ------------------------------
// 1 CTA/SM, 148 persistent CTAs. Per M-tile (64 nodes): phase 1 = K=16 mma
// builds h1 (64x256) into As; phase 2 = [t|u] = As @ Bs (full Wc SMEM-resident),
// warp tile 32x64, zero global B traffic, zero syncs in K loop.
__global__ void __launch_bounds__(256) k_gemm(
        const float* __restrict__ pos, const float* __restrict__ W1l,
        const float* __restrict__ W1r, const float* __restrict__ b1) {
    extern __shared__ __half sm[];
    __half* W1s = sm + W1S_OFF;   // [16][ASTR]
    __half* As  = sm + AS_OFF;    // [64][ASTR]
    __half* Bs  = sm + BS_OFF;    // [256][ASTR]  (full Wc, K-major)

    int tid = threadIdx.x;
    int warp = tid >> 5, lane = tid & 31;
    int wm = warp & 1;            // 2 M-warps (32 rows each)
    int wn = warp >> 1;           // 4 N-warps (64 cols each)

    // one-time: W1 tile (16x256; rows 0-2 W1l, 3-5 W1r, 6 b1, 7-15 = 0)
    #pragma unroll
    for (int j = 0; j < 2; j++) {
        int idx = tid + 256 * j;
        int row = idx >> 5, cq = idx & 31;
        int c = cq * 8;
        float v[8];
        #pragma unroll
        for (int q = 0; q < 8; q++) {
            float w = 0.0f;
            if (row < 3)       w = W1l[row * 256 + c + q];
            else if (row < 6)  w = W1r[(row - 3) * 256 + c + q];
            else if (row == 6) w = b1[c + q];
            v[q] = w;
        }
        __half2 h0 = __floats2half2_rn(v[0], v[1]);
        __half2 h1 = __floats2half2_rn(v[2], v[3]);
        __half2 h2 = __floats2half2_rn(v[4], v[5]);
        __half2 h3 = __floats2half2_rn(v[6], v[7]);
        *(uint4*)(W1s + row * ASTR + c) = make_uint4(*(unsigned*)&h0, *(unsigned*)&h1,
                                                     *(unsigned*)&h2, *(unsigned*)&h3);
    }
    // one-time: full Wc (256 x 256 fp16), 32 uint4 per thread
    #pragma unroll
    for (int j = 0; j < 32; j++) {
        int idx = tid + 256 * j;
        int row = idx >> 5, cq = idx & 31;
        *(uint4*)(Bs + row * ASTR + cq * 8) =
            *(const uint4*)(g_Wc + (size_t)row * 256 + cq * 8);
    }

    for (int mt = blockIdx.x; mt < NTILES; mt += gridDim.x) {
        int bm = mt * BM;
        __syncthreads();   // prior tile's phase-2 reads of As complete

        if (tid < 64) {
            int node = bm + tid;
            __half2 xy = g_s1h[2 * node + 0];
            __half2 zc = g_s1h[2 * node + 1];
            float deg = __half2float(__high2half(zc));
            float inv = 1.0f / fmaxf(deg, 1.0f);
            float ax = __half2float(__low2half(xy)) * inv;
            float ay = __half2float(__high2half(xy)) * inv;
            float az = __half2float(__low2half(zc)) * inv;
            float px = pos[3 * node + 0], py = pos[3 * node + 1], pz = pos[3 * node + 2];
            __half2 c01 = __floats2half2_rn(ax, ay);
            __half2 c23 = __floats2half2_rn(az, px);
            __half2 c45 = __floats2half2_rn(py, pz);
            __half2 c67 = __floats2half2_rn(1.0f, 0.0f);
            *(uint4*)(As + tid * ASTR + 0) = make_uint4(*(unsigned*)&c01, *(unsigned*)&c23,
                                                        *(unsigned*)&c45, *(unsigned*)&c67);
            *(uint4*)(As + tid * ASTR + 8) = make_uint4(0, 0, 0, 0);
        }
        __syncthreads();

        // phase 1: K=16 mma -> h1 fragments (64x256, warp tile 32x64)
        float acc[2][8][4];
        #pragma unroll
        for (int mi = 0; mi < 2; mi++)
            #pragma unroll
            for (int ni = 0; ni < 8; ni++)
                #pragma unroll
                for (int q = 0; q < 4; q++) acc[mi][ni][q] = 0.0f;
        {
            uint32_t a[2][4];
            #pragma unroll
            for (int mi = 0; mi < 2; mi++) {
                int r = wm * 32 + mi * 16 + (lane & 7) + 8 * ((lane >> 3) & 1);
                int cc = 8 * (lane >> 4);
                uint32_t addr = (uint32_t)__cvta_generic_to_shared(As + r * ASTR + cc);
                asm volatile("ldmatrix.sync.aligned.m8n8.x4.shared.b16 {%0,%1,%2,%3}, [%4];"
                             : "=r"(a[mi][0]), "=r"(a[mi][1]), "=r"(a[mi][2]), "=r"(a[mi][3])
                             : "r"(addr));
            }
            int rr = (lane & 7) + 8 * ((lane >> 3) & 1);
            #pragma unroll
            for (int np = 0; np < 4; np++) {
                int ncol = wn * 64 + np * 16 + 8 * (lane >> 4);
                uint32_t b[4];
                uint32_t baddr = (uint32_t)__cvta_generic_to_shared(W1s + rr * ASTR + ncol);
                asm volatile("ldmatrix.sync.aligned.m8n8.x4.trans.shared.b16 {%0,%1,%2,%3}, [%4];"
                             : "=r"(b[0]), "=r"(b[1]), "=r"(b[2]), "=r"(b[3])
                             : "r"(baddr));
                #pragma unroll
                for (int mi = 0; mi < 2; mi++) {
                    #pragma unroll
                    for (int h = 0; h < 2; h++) {
                        int ni = np * 2 + h;
                        asm volatile(
                            "mma.sync.aligned.m16n8k16.row.col.f32.f16.f16.f32 "
                            "{%0,%1,%2,%3},{%4,%5,%6,%7},{%8,%9},{%0,%1,%2,%3};"
                            : "+f"(acc[mi][ni][0]), "+f"(acc[mi][ni][1]),
                              "+f"(acc[mi][ni][2]), "+f"(acc[mi][ni][3])
                            : "r"(a[mi][0]), "r"(a[mi][1]), "r"(a[mi][2]), "r"(a[mi][3]),
                              "r"(b[2 * h]), "r"(b[2 * h + 1]));
                    }
                }
            }
        }
        __syncthreads();

        // relu + store h1 fragments into As (full 64 x 256)
        {
            int gid = lane >> 2, qid = lane & 3;
            #pragma unroll
            for (int mi = 0; mi < 2; mi++) {
                int r0 = wm * 32 + mi * 16 + gid;
                int r1 = r0 + 8;
                #pragma unroll
                for (int ni = 0; ni < 8; ni++) {
                    int col = wn * 64 + ni * 8 + qid * 2;
                    __half2 p0 = __floats2half2_rn(fmaxf(acc[mi][ni][0], 0.0f),
                                                   fmaxf(acc[mi][ni][1], 0.0f));
                    *(unsigned*)(As + r0 * ASTR + col) = *(unsigned*)&p0;
                    __half2 p1 = __floats2half2_rn(fmaxf(acc[mi][ni][2], 0.0f),
                                                   fmaxf(acc[mi][ni][3], 0.0f));
                    *(unsigned*)(As + r1 * ASTR + col) = *(unsigned*)&p1;
                }
            }
        }
        __syncthreads();

        // phase 2: [t|u] = As @ Bs; K=256, warp tile 32x64, all SMEM, no syncs
        #pragma unroll
        for (int mi = 0; mi < 2; mi++)
            #pragma unroll
            for (int ni = 0; ni < 8; ni++)
                #pragma unroll
                for (int q = 0; q < 4; q++) acc[mi][ni][q] = 0.0f;

        #pragma unroll 2
        for (int k0 = 0; k0 < KH; k0 += 16) {
            uint32_t a[2][4];
            #pragma unroll
            for (int mi = 0; mi < 2; mi++) {
                int r = wm * 32 + mi * 16 + (lane & 7) + 8 * ((lane >> 3) & 1);
                int cc = k0 + 8 * (lane >> 4);
                uint32_t addr = (uint32_t)__cvta_generic_to_shared(As + r * ASTR + cc);
                asm volatile("ldmatrix.sync.aligned.m8n8.x4.shared.b16 {%0,%1,%2,%3}, [%4];"
                             : "=r"(a[mi][0]), "=r"(a[mi][1]), "=r"(a[mi][2]), "=r"(a[mi][3])
                             : "r"(addr));
            }
            int rr = k0 + (lane & 7) + 8 * ((lane >> 3) & 1);
            #pragma unroll
            for (int np = 0; np < 4; np++) {
                int ncol = wn * 64 + np * 16 + 8 * (lane >> 4);
                uint32_t b[4];
                uint32_t baddr = (uint32_t)__cvta_generic_to_shared(Bs + rr * ASTR + ncol);
                asm volatile("ldmatrix.sync.aligned.m8n8.x4.trans.shared.b16 {%0,%1,%2,%3}, [%4];"
                             : "=r"(b[0]), "=r"(b[1]), "=r"(b[2]), "=r"(b[3])
                             : "r"(baddr));
                #pragma unroll
                for (int mi = 0; mi < 2; mi++) {
                    #pragma unroll
                    for (int h = 0; h < 2; h++) {
                        int ni = np * 2 + h;
                        asm volatile(
                            "mma.sync.aligned.m16n8k16.row.col.f32.f16.f16.f32 "
                            "{%0,%1,%2,%3},{%4,%5,%6,%7},{%8,%9},{%0,%1,%2,%3};"
                            : "+f"(acc[mi][ni][0]), "+f"(acc[mi][ni][1]),
                              "+f"(acc[mi][ni][2]), "+f"(acc[mi][ni][3])
                            : "r"(a[mi][0]), "r"(a[mi][1]), "r"(a[mi][2]), "r"(a[mi][3]),
                              "r"(b[2 * h]), "r"(b[2 * h + 1]));
                    }
                }
            }
        }

        // epilogue: cols <128 -> g_t8 (fp8 e4m3), cols >=128 -> g_u (fp16)
        {
            int gid = lane >> 2, qid = lane & 3;
            #pragma unroll
            for (int mi = 0; mi < 2; mi++) {
                int r0 = bm + wm * 32 + mi * 16 + gid;
                int r1 = r0 + 8;
                #pragma unroll
                for (int ni = 0; ni < 8; ni++) {
                    int col = wn * 64 + ni * 8 + qid * 2;
                    if (col < 128) {
                        __nv_fp8x2_storage_t q0 = __nv_cvt_float2_to_fp8x2(
                            make_float2(acc[mi][ni][0], acc[mi][ni][1]),
                            __NV_SATFINITE, __NV_E4M3);
                        *(unsigned short*)(g_t8 + (size_t)r0 * 128 + col) = q0;
                        __nv_fp8x2_storage_t q1 = __nv_cvt_float2_to_fp8x2(
                            make_float2(acc[mi][ni][2], acc[mi][ni][3]),
                            __NV_SATFINITE, __NV_E4M3);
                        *(unsigned short*)(g_t8 + (size_t)r1 * 128 + col) = q1;
                    } else {
                        int cc = col - 128;
                        __half2 p0 = __floats2half2_rn(acc[mi][ni][0], acc[mi][ni][1]);
                        *(unsigned*)(g_u + (size_t)r0 * 128 + cc) = *(unsigned*)&p0;
                        __half2 p1 = __floats2half2_rn(acc[mi][ni][2], acc[mi][ni][3]);
                        *(unsigned*)(g_u + (size_t)r1 * 128 + cc) = *(unsigned*)&p1;
                    }
                }
            }
        }
    }
}

// ---- L5: layer-2 aggregate (fp8 gather) + relu + mean-pool (+ restore s1h) ----
__global__ void k_layer2(const float* __restrict__ b2) {
    __shared__ float gsh[128];
    if (threadIdx.x < 128) gsh[threadIdx.x] = 0.0f;
    __syncthreads();

    int wid = threadIdx.x >> 5, lane = threadIdx.x & 31;
    int gwarp = blockIdx.x * (blockDim.x >> 5) + wid;
    int nwarps = gridDim.x * (blockDim.x >> 5);
    float4 bl = ((const float4*)b2)[lane];

    float a0 = 0.f, a1 = 0.f, a2 = 0.f, a3 = 0.f;
    for (int node = gwarp; node < NN; node += nwarps) {
        int beg = g_rowptr[node], end = g_rowptr[node + 1];
        if (lane == 0) {                 // restore invariants (gemm done reading)
            g_s1h[2 * node + 0] = __floats2half2_rn(0.0f, 0.0f);
            g_s1h[2 * node + 1] = __floats2half2_rn(0.0f, 0.0f);
        }
        float s0 = 0.f, s1 = 0.f, s2 = 0.f, s3 = 0.f;
        #pragma unroll 4
        for (int j = beg; j < end; j++) {
            int src = g_colidx[j];
            unsigned tv = *(const unsigned*)(g_t8 + (size_t)src * 128 + lane * 4);
            __half2_raw r01 = __nv_cvt_fp8x2_to_halfraw2(
                (__nv_fp8x2_storage_t)(tv & 0xFFFFu), __NV_E4M3);
            __half2_raw r23 = __nv_cvt_fp8x2_to_halfraw2(
                (__nv_fp8x2_storage_t)(tv >> 16), __NV_E4M3);
            float2 t01 = __half22float2(*(__half2*)&r01);
            float2 t23 = __half22float2(*(__half2*)&r23);
            s0 += t01.x; s1 += t01.y;
            s2 += t23.x; s3 += t23.y;
        }
        float inv = 1.0f / fmaxf((float)(end - beg), 1.0f);
        uint2 uv = ((const uint2*)(g_u + (size_t)node * 128))[lane];
        float2 u01 = __half22float2(*(__half2*)&uv.x);
        float2 u23 = __half22float2(*(__half2*)&uv.y);
        a0 += fmaxf(s0 * inv + u01.x + bl.x, 0.0f);
        a1 += fmaxf(s1 * inv + u01.y + bl.y, 0.0f);
        a2 += fmaxf(s2 * inv + u23.x + bl.z, 0.0f);
        a3 += fmaxf(s3 * inv + u23.y + bl.w, 0.0f);
    }
    atomicAdd(&gsh[lane * 4 + 0], a0);
    atomicAdd(&gsh[lane * 4 + 1], a1);
    atomicAdd(&gsh[lane * 4 + 2], a2);
    atomicAdd(&gsh[lane * 4 + 3], a3);
    __syncthreads();
    if (threadIdx.x < 128) atomicAdd(&g_gsum[threadIdx.x], gsh[threadIdx.x]);
}

// ---- L6: decoder + softmax + argmax (+ restore gsum) ---------------------------
__global__ void k_final(const float* __restrict__ Wd, const float* __restrict__ bd,
                        float* __restrict__ out, int out_size) {
    if (threadIdx.x != 0 || blockIdx.x != 0) return;
    float g[128];
    for (int c = 0; c < 128; c++) {
        g[c] = g_gsum[c] * (1.0f / (float)NN);
        g_gsum[c] = 0.0f;   // restore invariant
    }
    float lg[10];
    for (int j = 0; j < 10; j++) lg[j] = bd[j];
    for (int c = 0; c < 128; c++) {
        float gv = g[c];
        for (int j = 0; j < 10; j++) lg[j] += gv * Wd[c * 10 + j];
    }
    float m = lg[0];
    for (int j = 1; j < 10; j++) m = fmaxf(m, lg[j]);
    float e[10], s = 0.0f;
    for (int j = 0; j < 10; j++) { e[j] = expf(lg[j] - m); s += e[j]; }
    float invs = 1.0f / s;
    int am = 0;
    float best = -1.0f;
    for (int j = 0; j < 10; j++) {
        float p = e[j] * invs;
        if (j < out_size) out[j] = p;
        if (p > best) { best = p; am = j; }
    }
    for (int i = 10; i < out_size; i++) out[i] = (float)am;
}

// ---------------- launch --------------------------------------------------------
extern "C" void kernel_launch(void* const* d_in, const int* in_sizes, int n_in,
                              void* d_out, int out_size) {
    const float* pos = (const float*)d_in[0];
    const int*   face = (const int*)d_in[1];
    const float* W1l = (const float*)d_in[2];
    const float* W1r = (const float*)d_in[3];
    const float* b1  = (const float*)d_in[4];
    const float* W2l = (const float*)d_in[5];
    const float* W2r = (const float*)d_in[6];
    const float* b2  = (const float*)d_in[7];
    const float* Wd  = (const float*)d_in[8];
    const float* bd  = (const float*)d_in[9];
    float* out = (float*)d_out;

    int dev = 0, nsm = 148;
    cudaGetDevice(&dev);
    cudaDeviceGetAttribute(&nsm, cudaDevAttrMultiProcessorCount, dev);
    cudaFuncSetAttribute(k_gemm, cudaFuncAttributeMaxDynamicSharedMemorySize, SM_TOTAL);

    k_hist   <<<(NF + 255) / 256, 256>>>(face, pos, W2l, W2r);     // 1
    k_scan   <<<NBLK, 1024>>>();                                   // 2
    k_fill   <<<(NF + 255) / 256, 256>>>(face);                    // 3
    k_gemm   <<<nsm, 256, SM_TOTAL>>>(pos, W1l, W1r, b1);          // 4  <- profiled
    k_layer2 <<<1184, 256>>>(b2);                                  // 5
    k_final  <<<1, 32>>>(Wd, bd, out, out_size);                   // 6
}